// round 15
// baseline (speedup 1.0000x reference)
#include <cuda_runtime.h>
#include <cuda_bf16.h>
#include <math.h>
#include <stdint.h>

#define NN 16384
#define DD 1024
#define KK 32
#define LL 16
#define WPAD 640
#define M2W 576
#define ZC 4
#define ZD 64
#define LOG2PI_F 1.8378770664093453f

// ---------------- device scratch ----------------
__device__ __align__(16) __nv_bfloat16 gXhi [NN][DD];
__device__ __align__(16) __nv_bfloat16 gXlo [NN][DD];
__device__ __align__(16) __nv_bfloat16 gXThi[DD][NN];
__device__ __align__(16) __nv_bfloat16 gXTlo[DD][NN];
__device__ __align__(16) __nv_bfloat16 gWThi[WPAD][DD];
__device__ __align__(16) __nv_bfloat16 gWTlo[WPAD][DD];
__device__ __align__(16) __nv_bfloat16 gM2Thi[M2W][NN];
__device__ __align__(16) __nv_bfloat16 gM2Tlo[M2W][NN];
__device__ float gCs[ZC][NN][WPAD];    // ZC K-slabs of [cross(32) | P(512)]
__device__ float gM2[NN][M2W];         // [rP(512) | r(32) | rx2(32)]
__device__ float gX2[NN];
__device__ float gSiAiP[DD][ZD][512];  // ZD k-split slabs of x^T(rP)
__device__ float gMuNum[DD][KK];       // x^T r (atomic)
__device__ float gSiAi2[KK][DD][LL];
__device__ float gmu[KK][DD];
__device__ float giL  [KK][LL][LL];
__device__ float gInvM[KK][LL][LL];
__device__ float gbmu [KK][LL];
__device__ float gG   [KK][LL];
__device__ float gmuSq[KK];
__device__ float giD [KK];
__device__ float gck[KK];
__device__ float gs2[KK];
__device__ float grsum[KK];
__device__ float grx2[KK];

// ---------------- helpers ----------------
__device__ __forceinline__ uint32_t s2u(const void* p) {
    uint32_t a;
    asm("{ .reg .u64 t; cvta.to.shared.u64 t, %1; cvt.u32.u64 %0, t; }" : "=r"(a) : "l"(p));
    return a;
}
__device__ __forceinline__ void ldm4(uint32_t* r, uint32_t addr) {
    asm volatile("ldmatrix.sync.aligned.m8n8.x4.shared.b16 {%0,%1,%2,%3}, [%4];"
                 : "=r"(r[0]), "=r"(r[1]), "=r"(r[2]), "=r"(r[3]) : "r"(addr));
}
__device__ __forceinline__ void mma16816(float* c, const uint32_t* a, uint32_t b0, uint32_t b1) {
    asm volatile(
        "mma.sync.aligned.m16n8k16.row.col.f32.bf16.bf16.f32 "
        "{%0,%1,%2,%3}, {%4,%5,%6,%7}, {%8,%9}, {%0,%1,%2,%3};"
        : "+f"(c[0]), "+f"(c[1]), "+f"(c[2]), "+f"(c[3])
        : "r"(a[0]), "r"(a[1]), "r"(a[2]), "r"(a[3]), "r"(b0), "r"(b1));
}
__device__ __forceinline__ void cpasync16(uint32_t smem, const void* g) {
    asm volatile("cp.async.cg.shared.global [%0], [%1], 16;" :: "r"(smem), "l"(g) : "memory");
}
#define CP_COMMIT() asm volatile("cp.async.commit_group;" ::: "memory")
#define CP_WAIT2()  asm volatile("cp.async.wait_group 2;" ::: "memory")

__device__ __forceinline__ float block_reduce_sum(float v, float* sbuf) {
    int t = threadIdx.x;
    sbuf[t] = v; __syncthreads();
    for (int s = 128; s > 0; s >>= 1) {
        if (t < s) sbuf[t] += sbuf[t + s];
        __syncthreads();
    }
    float r = sbuf[0];
    __syncthreads();
    return r;
}
__device__ void block_invert16(float aug[16][32], float* slogdet, float* sfac, int* spiv) {
    int t = threadIdx.x;
    int r = t >> 4, c = t & 15;
    for (int p = 0; p < 16; ++p) {
        __syncthreads();
        if (t < 32) {
            float v = (t < 16 && t >= p) ? fabsf(aug[t][p]) : -1.f;
            int idx = t;
            #pragma unroll
            for (int off = 8; off > 0; off >>= 1) {
                float ov = __shfl_xor_sync(0xffffffffu, v, off);
                int oi = __shfl_xor_sync(0xffffffffu, idx, off);
                if (ov > v) { v = ov; idx = oi; }
            }
            if (t == 0) {
                *spiv = idx;
                if (slogdet) *slogdet += logf(fmaxf(v, 1e-30f));
            }
        }
        __syncthreads();
        int pr = *spiv;
        if (pr != p && t < 32) { float tmp = aug[p][t]; aug[p][t] = aug[pr][t]; aug[pr][t] = tmp; }
        __syncthreads();
        if (t < 32) {
            float val = aug[p][t];
            float pv  = aug[p][p];
            __syncwarp();
            aug[p][t] = val / pv;
        }
        __syncthreads();
        if (c == 0) sfac[r] = aug[r][p];
        __syncthreads();
        if (r != p) {
            float f = sfac[r];
            aug[r][c]      -= f * aug[p][c];
            aug[r][c + 16] -= f * aug[p][c + 16];
        }
    }
    __syncthreads();
}

// ---------------- kernel 0: zero scratch ----------------
__global__ void zero_kernel() {
    int i0 = blockIdx.x * 256 + threadIdx.x;
    int str = gridDim.x * 256;
    for (int i = i0; i < DD * KK; i += str) (&gMuNum[0][0])[i] = 0.f;
    if (i0 < KK) { grsum[i0] = 0.f; grx2[i0] = 0.f; }
    if (i0 < KK * LL) (&gG[0][0])[i0] = 0.f;
}

// ---------------- straight split + x2 (critical path) ----------------
__global__ void __launch_bounds__(256) xprep_straight(const float* __restrict__ x) {
    int warp = threadIdx.x >> 5, lane = threadIdx.x & 31;
    int n = blockIdx.x * 8 + warp;
    const float4* xr = (const float4*)(x + (size_t)n * DD);
    float s = 0.f;
    #pragma unroll
    for (int c = lane; c < 256; c += 32) {
        float4 v = xr[c];
        s += v.x * v.x + v.y * v.y + v.z * v.z + v.w * v.w;
        __nv_bfloat16 h0 = __float2bfloat16(v.x), h1 = __float2bfloat16(v.y);
        __nv_bfloat16 h2 = __float2bfloat16(v.z), h3 = __float2bfloat16(v.w);
        ushort4 ph, pl;
        ph.x = __bfloat16_as_ushort(h0); ph.y = __bfloat16_as_ushort(h1);
        ph.z = __bfloat16_as_ushort(h2); ph.w = __bfloat16_as_ushort(h3);
        pl.x = __bfloat16_as_ushort(__float2bfloat16(v.x - __bfloat162float(h0)));
        pl.y = __bfloat16_as_ushort(__float2bfloat16(v.y - __bfloat162float(h1)));
        pl.z = __bfloat16_as_ushort(__float2bfloat16(v.z - __bfloat162float(h2)));
        pl.w = __bfloat16_as_ushort(__float2bfloat16(v.w - __bfloat162float(h3)));
        *(ushort4*)(&gXhi[n][c * 4]) = ph;
        *(ushort4*)(&gXlo[n][c * 4]) = pl;
    }
    #pragma unroll
    for (int off = 16; off > 0; off >>= 1) s += __shfl_xor_sync(0xffffffffu, s, off);
    if (lane == 0) gX2[n] = s;
}

// ---------------- transposed split (side stream 1) ----------------
__global__ void __launch_bounds__(256) xprep_T(const float* __restrict__ x) {
    __shared__ float tile[32][33];
    int t = threadIdx.x;
    int tx8 = t & 7, ty = t >> 3;
    int c0 = blockIdx.x * 32, r0 = blockIdx.y * 32;
    float4 v = *(const float4*)(x + (size_t)(r0 + ty) * DD + c0 + tx8 * 4);
    tile[ty][tx8 * 4 + 0] = v.x;
    tile[ty][tx8 * 4 + 1] = v.y;
    tile[ty][tx8 * 4 + 2] = v.z;
    tile[ty][tx8 * 4 + 3] = v.w;
    __syncthreads();
    int cc = t >> 3, rq = (t & 7) * 4;
    float w0 = tile[rq + 0][cc], w1 = tile[rq + 1][cc];
    float w2 = tile[rq + 2][cc], w3 = tile[rq + 3][cc];
    __nv_bfloat16 g0 = __float2bfloat16(w0), g1 = __float2bfloat16(w1);
    __nv_bfloat16 g2 = __float2bfloat16(w2), g3 = __float2bfloat16(w3);
    ushort4 qh, ql;
    qh.x = __bfloat16_as_ushort(g0); qh.y = __bfloat16_as_ushort(g1);
    qh.z = __bfloat16_as_ushort(g2); qh.w = __bfloat16_as_ushort(g3);
    ql.x = __bfloat16_as_ushort(__float2bfloat16(w0 - __bfloat162float(g0)));
    ql.y = __bfloat16_as_ushort(__float2bfloat16(w1 - __bfloat162float(g1)));
    ql.z = __bfloat16_as_ushort(__float2bfloat16(w2 - __bfloat162float(g2)));
    ql.w = __bfloat16_as_ushort(__float2bfloat16(w3 - __bfloat162float(g3)));
    *(ushort4*)(&gXThi[c0 + cc][r0 + rq]) = qh;
    *(ushort4*)(&gXTlo[c0 + cc][r0 + rq]) = ql;
}

// ---------------- per-k setup (side stream 2), 64-row-chunked ----------------
__global__ void setup_kernel(const float* __restrict__ MU, const float* __restrict__ A,
                             const float* __restrict__ log_D, const float* __restrict__ PI_logits) {
    int k = blockIdx.x, t = threadIdx.x;
    __shared__ float sred[256];
    __shared__ float sPIk;
    if (t == 0) {
        float mx = -1e30f;
        for (int j = 0; j < KK; ++j) mx = fmaxf(mx, PI_logits[j]);
        float s = 0.f;
        for (int j = 0; j < KK; ++j) s += expf(PI_logits[j] - mx);
        sPIk = expf(PI_logits[k] - mx) / s;
    }
    float ld0 = log_D[(size_t)k * DD];
    float iD = expf(-ld0);
    float s2 = expf(ld0);
    float muSqAcc = 0.f;
    for (int d = t; d < DD; d += 256) {
        float mu = MU[(size_t)k * DD + d];
        __nv_bfloat16 h = __float2bfloat16(mu);
        gWThi[k][d] = h;
        gWTlo[k][d] = __float2bfloat16(mu - __bfloat162float(h));
        muSqAcc += mu * mu;
    }
    __shared__ float sA[64][17];
    int li = t >> 4, mi = t & 15;
    float ATAacc = 0.f, bmuAcc = 0.f;
    const int lw = t >> 4;
    const int dq = (t & 15) * 4;
    for (int c0 = 0; c0 < DD; c0 += 64) {
        __syncthreads();
        {
            int row = t >> 2, q = (t & 3) * 4;
            float4 a4 = *(const float4*)(A + ((size_t)k * DD + c0 + row) * LL + q);
            sA[row][q + 0] = a4.x;
            sA[row][q + 1] = a4.y;
            sA[row][q + 2] = a4.z;
            sA[row][q + 3] = a4.w;
        }
        __syncthreads();
        {
            float4 m4 = *(const float4*)(MU + (size_t)k * DD + c0 + dq);
            float a0 = sA[dq + 0][lw], a1 = sA[dq + 1][lw];
            float a2 = sA[dq + 2][lw], a3 = sA[dq + 3][lw];
            bmuAcc += m4.x * a0 + m4.y * a1 + m4.z * a2 + m4.w * a3;
            __nv_bfloat16 h0 = __float2bfloat16(a0), h1 = __float2bfloat16(a1);
            __nv_bfloat16 h2 = __float2bfloat16(a2), h3 = __float2bfloat16(a3);
            ushort4 ph, pl;
            ph.x = __bfloat16_as_ushort(h0); ph.y = __bfloat16_as_ushort(h1);
            ph.z = __bfloat16_as_ushort(h2); ph.w = __bfloat16_as_ushort(h3);
            pl.x = __bfloat16_as_ushort(__float2bfloat16(a0 - __bfloat162float(h0)));
            pl.y = __bfloat16_as_ushort(__float2bfloat16(a1 - __bfloat162float(h1)));
            pl.z = __bfloat16_as_ushort(__float2bfloat16(a2 - __bfloat162float(h2)));
            pl.w = __bfloat16_as_ushort(__float2bfloat16(a3 - __bfloat162float(h3)));
            *(ushort4*)(&gWThi[32 + k * 16 + lw][c0 + dq]) = ph;
            *(ushort4*)(&gWTlo[32 + k * 16 + lw][c0 + dq]) = pl;
        }
        #pragma unroll
        for (int dd = 0; dd < 64; ++dd) ATAacc += sA[dd][li] * sA[dd][mi];
    }
    float muSqK = block_reduce_sum(muSqAcc, sred);
    __shared__ float sbm[16][17];
    sbm[lw][t & 15] = bmuAcc;
    __syncthreads();
    if (t < 16) {
        float s = 0.f;
        for (int g = 0; g < 16; ++g) s += sbm[t][g];
        gbmu[k][t] = s;
    }
    __shared__ float aug[16][32];
    __shared__ float sfac[16];
    __shared__ int spiv;
    __shared__ float slogdet;
    if (t == 0) slogdet = 0.f;
    __syncthreads();
    aug[li][mi]      = iD * ATAacc + (li == mi ? 1.f : 0.f);
    aug[li][16 + mi] = (li == mi ? 1.f : 0.f);
    block_invert16(aug, &slogdet, sfac, &spiv);
    giL[k][li][mi] = aug[li][16 + mi];
    float logdetL = slogdet;
    __syncthreads();
    aug[li][mi]      = ATAacc + (li == mi ? s2 : 0.f);
    aug[li][16 + mi] = (li == mi ? 1.f : 0.f);
    block_invert16(aug, nullptr, sfac, &spiv);
    gInvM[k][li][mi] = aug[li][16 + mi];
    if (t == 0) {
        gmuSq[k] = muSqK;
        giD[k] = iD;
        gs2[k] = s2;
        gck[k] = sPIk - 0.5f * ((float)DD * LOG2PI_F + logdetL + (float)DD * ld0);
    }
}

// ---------------- fused mma GEMM: fat 128x128 tiles (y<4) + skinny 128x32 (y==4) ----------------
#define SR16 24
#define STG_AHI 0
#define STG_ALO 6144
#define STG_BHI 12288
#define STG_BLO 18432
#define STGSZ   24576
#define NSTAGE  4

__global__ void __launch_bounds__(256, 2) mma_gemm_fused(
    const __nv_bfloat16* __restrict__ Ahi, const __nv_bfloat16* __restrict__ Alo, int lda,
    const __nv_bfloat16* __restrict__ Bhi, const __nv_bfloat16* __restrict__ Blo, int ldb,
    float* __restrict__ C, int ldc, int zstride, int nOffFat,
    float* __restrict__ Cs, int ldcs, int zstrideS, int bOffS, int atomicS,
    int kLen)
{
    extern __shared__ __align__(128) char ds[];
    const uint32_t sbase = s2u(ds);
    const int t = threadIdx.x, lane = t & 31, w = t >> 5;
    const int m0 = blockIdx.x * 128;
    const int kBeg = blockIdx.z * kLen;
    const int nCh = kLen >> 4;

    if (blockIdx.y < 4) {
        const int wm = w & 1, wn = w >> 1;
        const int n0 = nOffFat + blockIdx.y * 128;
        float* Cf = C + (size_t)blockIdx.z * zstride;

        const int row = t >> 1, half = (t & 1) * 8;
        const size_t gA = (size_t)(m0 + row) * lda + kBeg + half;
        const size_t gB = (size_t)(n0 + row) * ldb + kBeg + half;
        const uint32_t soff = (uint32_t)(row * SR16 + half) * 2;
        const int aoff0 = ((wm * 64 + (lane & 15)) * SR16 + ((lane >> 4) << 3)) * 2;
        const int boff0 = ((wn * 32 + (lane & 15)) * SR16 + ((lane >> 4) << 3)) * 2;

        float acc[4][4][4] = {};

        #pragma unroll
        for (int st = 0; st < NSTAGE - 1; ++st) {
            uint32_t sb = sbase + st * STGSZ;
            int kk = st * 16;
            cpasync16(sb + STG_AHI + soff, Ahi + gA + kk);
            cpasync16(sb + STG_ALO + soff, Alo + gA + kk);
            cpasync16(sb + STG_BHI + soff, Bhi + gB + kk);
            cpasync16(sb + STG_BLO + soff, Blo + gB + kk);
            CP_COMMIT();
        }
        for (int ch = 0; ch < nCh; ++ch) {
            CP_WAIT2();
            __syncthreads();
            const uint32_t sb = sbase + (ch & 3) * STGSZ;
            uint32_t ah[4][4], al[4][4], bh[2][4], bl[2][4];
            #pragma unroll
            for (int p = 0; p < 2; ++p) {
                ldm4(bh[p], sb + STG_BHI + boff0 + p * 16 * SR16 * 2);
                ldm4(bl[p], sb + STG_BLO + boff0 + p * 16 * SR16 * 2);
            }
            #pragma unroll
            for (int mf = 0; mf < 4; ++mf) {
                ldm4(ah[mf], sb + STG_AHI + aoff0 + mf * 16 * SR16 * 2);
                ldm4(al[mf], sb + STG_ALO + aoff0 + mf * 16 * SR16 * 2);
            }
            #pragma unroll
            for (int mf = 0; mf < 4; ++mf)
                #pragma unroll
                for (int nf = 0; nf < 4; ++nf) {
                    int p = nf >> 1, o = nf & 1;
                    mma16816(acc[mf][nf], ah[mf], bh[p][o], bh[p][2 + o]);
                }
            #pragma unroll
            for (int mf = 0; mf < 4; ++mf)
                #pragma unroll
                for (int nf = 0; nf < 4; ++nf) {
                    int p = nf >> 1, o = nf & 1;
                    mma16816(acc[mf][nf], ah[mf], bl[p][o], bl[p][2 + o]);
                }
            #pragma unroll
            for (int mf = 0; mf < 4; ++mf)
                #pragma unroll
                for (int nf = 0; nf < 4; ++nf) {
                    int p = nf >> 1, o = nf & 1;
                    mma16816(acc[mf][nf], al[mf], bh[p][o], bh[p][2 + o]);
                }
            int st = ch + NSTAGE - 1;
            if (st < nCh) {
                uint32_t sn = sbase + (st & 3) * STGSZ;
                int kk = st * 16;
                cpasync16(sn + STG_AHI + soff, Ahi + gA + kk);
                cpasync16(sn + STG_ALO + soff, Alo + gA + kk);
                cpasync16(sn + STG_BHI + soff, Bhi + gB + kk);
                cpasync16(sn + STG_BLO + soff, Blo + gB + kk);
            }
            CP_COMMIT();
        }
        const int gid = lane >> 2, tid = lane & 3;
        #pragma unroll
        for (int mf = 0; mf < 4; ++mf) {
            #pragma unroll
            for (int nf = 0; nf < 4; ++nf) {
                int rr = m0 + wm * 64 + mf * 16 + gid;
                int col = n0 + wn * 32 + nf * 8 + tid * 2;
                float* c0 = Cf + (size_t)rr * ldc + col;
                float* c1 = Cf + (size_t)(rr + 8) * ldc + col;
                *(float2*)c0 = make_float2(acc[mf][nf][0], acc[mf][nf][1]);
                *(float2*)c1 = make_float2(acc[mf][nf][2], acc[mf][nf][3]);
            }
        }
    } else {
        const int wm = w >> 1, wn = w & 1;
        float* Csf = Cs + (size_t)blockIdx.z * zstrideS;
        const int row = t >> 1, half = (t & 1) * 8;
        const size_t gA = (size_t)(m0 + row) * lda + kBeg + half;
        const uint32_t soffA = (uint32_t)(row * SR16 + half) * 2;
        const int rowB = (t & 63) >> 1;
        const size_t gB = (size_t)(bOffS + rowB) * ldb + kBeg + half;
        const uint32_t soffB = (uint32_t)(rowB * SR16 + half) * 2;
        const bool doB = (t < 64);
        const int aoff0 = ((wm * 32 + (lane & 15)) * SR16 + ((lane >> 4) << 3)) * 2;
        const int boff0 = ((wn * 16 + (lane & 15)) * SR16 + ((lane >> 4) << 3)) * 2;

        float acc[2][2][4] = {};

        #pragma unroll
        for (int st = 0; st < NSTAGE - 1; ++st) {
            uint32_t sb = sbase + st * STGSZ;
            int kk = st * 16;
            cpasync16(sb + STG_AHI + soffA, Ahi + gA + kk);
            cpasync16(sb + STG_ALO + soffA, Alo + gA + kk);
            if (doB) {
                cpasync16(sb + STG_BHI + soffB, Bhi + gB + kk);
                cpasync16(sb + STG_BLO + soffB, Blo + gB + kk);
            }
            CP_COMMIT();
        }
        for (int ch = 0; ch < nCh; ++ch) {
            CP_WAIT2();
            __syncthreads();
            const uint32_t sb = sbase + (ch & 3) * STGSZ;
            uint32_t ah[2][4], al[2][4], bh[4], bl[4];
            ldm4(bh, sb + STG_BHI + boff0);
            ldm4(bl, sb + STG_BLO + boff0);
            #pragma unroll
            for (int mf = 0; mf < 2; ++mf) {
                ldm4(ah[mf], sb + STG_AHI + aoff0 + mf * 16 * SR16 * 2);
                ldm4(al[mf], sb + STG_ALO + aoff0 + mf * 16 * SR16 * 2);
            }
            #pragma unroll
            for (int mf = 0; mf < 2; ++mf)
                #pragma unroll
                for (int nf = 0; nf < 2; ++nf)
                    mma16816(acc[mf][nf], ah[mf], bh[nf], bh[2 + nf]);
            #pragma unroll
            for (int mf = 0; mf < 2; ++mf)
                #pragma unroll
                for (int nf = 0; nf < 2; ++nf)
                    mma16816(acc[mf][nf], ah[mf], bl[nf], bl[2 + nf]);
            #pragma unroll
            for (int mf = 0; mf < 2; ++mf)
                #pragma unroll
                for (int nf = 0; nf < 2; ++nf)
                    mma16816(acc[mf][nf], al[mf], bh[nf], bh[2 + nf]);
            int st = ch + NSTAGE - 1;
            if (st < nCh) {
                uint32_t sn = sbase + (st & 3) * STGSZ;
                int kk = st * 16;
                cpasync16(sn + STG_AHI + soffA, Ahi + gA + kk);
                cpasync16(sn + STG_ALO + soffA, Alo + gA + kk);
                if (doB) {
                    cpasync16(sn + STG_BHI + soffB, Bhi + gB + kk);
                    cpasync16(sn + STG_BLO + soffB, Blo + gB + kk);
                }
            }
            CP_COMMIT();
        }
        const int gid = lane >> 2, tid = lane & 3;
        #pragma unroll
        for (int mf = 0; mf < 2; ++mf) {
            #pragma unroll
            for (int nf = 0; nf < 2; ++nf) {
                int rr = m0 + wm * 32 + mf * 16 + gid;
                int col = wn * 16 + nf * 8 + tid * 2;
                float* c0 = Csf + (size_t)rr * ldcs + col;
                float* c1 = Csf + (size_t)(rr + 8) * ldcs + col;
                if (atomicS) {
                    atomicAdd(c0,     acc[mf][nf][0]);
                    atomicAdd(c0 + 1, acc[mf][nf][1]);
                    atomicAdd(c1,     acc[mf][nf][2]);
                    atomicAdd(c1 + 1, acc[mf][nf][3]);
                } else {
                    *(float2*)c0 = make_float2(acc[mf][nf][0], acc[mf][nf][1]);
                    *(float2*)c1 = make_float2(acc[mf][nf][2], acc[mf][nf][3]);
                }
            }
        }
    }
}

// ---------------- E-step epilogue (sums the ZC gC slabs) ----------------
__global__ void __launch_bounds__(256) estep_epilogue() {
    __shared__ float siLs[KK * 272];
    __shared__ float sbmu_[KK][LL];
    __shared__ float smuSq_[KK];
    __shared__ float siD_[KK];
    __shared__ float sck_[KK];
    __shared__ float sll[8][32];
    int t = threadIdx.x;
    for (int idx = t; idx < KK * 256; idx += 256) {
        int kk = idx >> 8, rem = idx & 255;
        siLs[kk * 272 + (rem >> 4) * 17 + (rem & 15)] = (&giL[0][0][0])[idx];
    }
    for (int idx = t; idx < KK * LL; idx += 256) (&sbmu_[0][0])[idx] = (&gbmu[0][0])[idx];
    if (t < KK) { smuSq_[t] = gmuSq[t]; sck_[t] = gck[t]; siD_[t] = giD[t]; }
    __syncthreads();

    int warp = t >> 5, lane = t & 31;
    int n = blockIdx.x * 8 + warp;
    const float* Cp[ZC];
    #pragma unroll
    for (int z = 0; z < ZC; ++z) Cp[z] = &gCs[z][n][0];
    float x2 = gX2[n];
    #pragma unroll 1
    for (int it = 0; it < 16; ++it) {
        int k = it * 2 + (lane >> 4);
        int gl = lane & 15;
        int jj = 32 + k * 16 + gl;
        float yv = -sbmu_[k][gl];
        #pragma unroll
        for (int z = 0; z < ZC; ++z) yv += Cp[z][jj];
        float zacc = 0.f;
        const float* ilr = &siLs[k * 272 + gl * 17];
        #pragma unroll
        for (int m = 0; m < 16; ++m) {
            float ym = __shfl_sync(0xffffffffu, yv, (lane & 16) | m);
            zacc += ilr[m] * ym;
        }
        float t2 = zacc * yv;
        #pragma unroll
        for (int off = 8; off > 0; off >>= 1) t2 += __shfl_xor_sync(0xffffffffu, t2, off);
        if (gl == 0) {
            float iD = siD_[k];
            float cross = 0.f;
            #pragma unroll
            for (int z = 0; z < ZC; ++z) cross += Cp[z][k];
            float term1 = iD * (x2 - 2.f * cross + smuSq_[k]);
            sll[warp][k] = sck_[k] - 0.5f * term1 + 0.5f * iD * iD * t2;
        }
    }
    __syncwarp();
    float llk = sll[warp][lane];
    float mx = llk;
    #pragma unroll
    for (int off = 16; off > 0; off >>= 1) mx = fmaxf(mx, __shfl_xor_sync(0xffffffffu, mx, off));
    float e = expf(llk - mx);
    float s = e;
    #pragma unroll
    for (int off = 16; off > 0; off >>= 1) s += __shfl_xor_sync(0xffffffffu, s, off);
    float r = e / s;
    float* Mrow = &gM2[n][0];
    Mrow[512 + lane] = r;
    Mrow[544 + lane] = r * x2;
    #pragma unroll
    for (int it = 0; it < 16; ++it) {
        int j = it * 32 + lane;
        float rk = __shfl_sync(0xffffffffu, r, j >> 4);
        float pv = 0.f;
        #pragma unroll
        for (int z = 0; z < ZC; ++z) pv += Cp[z][32 + j];
        Mrow[j] = rk * pv;
    }
}

// ---------------- transpose-split M2 + fused column sums ----------------
__global__ void __launch_bounds__(256) tsplit_m2_kernel() {
    __shared__ float tile[32][33];
    int t = threadIdx.x;
    int tx = t & 31, ty = t >> 5;
    int c0 = blockIdx.x * 32;
    int r0 = blockIdx.y * 32;
    #pragma unroll
    for (int j = 0; j < 32; j += 8)
        tile[ty + j][tx] = gM2[r0 + ty + j][c0 + tx];
    __syncthreads();
    #pragma unroll
    for (int j = 0; j < 32; j += 8) {
        int wcol = c0 + ty + j;
        int h = r0 + tx;
        float v = tile[tx][ty + j];
        __nv_bfloat16 hi = __float2bfloat16(v);
        gM2Thi[wcol][h] = hi;
        gM2Tlo[wcol][h] = __float2bfloat16(v - __bfloat162float(hi));
    }
    if (t < 32) {
        int col = c0 + t;
        float s = 0.f;
        #pragma unroll
        for (int rr = 0; rr < 32; ++rr) s += tile[rr][t];
        if (col < 512)      atomicAdd(&gG[0][0] + col, s);
        else if (col < 544) atomicAdd(&grsum[col - 512], s);
        else                atomicAdd(&grx2[col - 544], s);
    }
}

// ---------------- finalize: sum ZD slabs, mu + SiAi ----------------
__global__ void __launch_bounds__(256) finalize_kernel(float* __restrict__ outMu) {
    __shared__ float sums[8][512];
    int t = threadIdx.x, warp = t >> 5, lane = t & 31;
    int d = blockIdx.x * 8 + warp;
    const float* base = &gSiAiP[d][0][0];
    for (int c = lane; c < 512; c += 32) {
        float s = 0.f;
        #pragma unroll
        for (int j = 0; j < ZD; ++j) s += base[j * 512 + c];
        sums[warp][c] = s;
    }
    {
        int k = lane;
        float mu = gMuNum[d][k] / grsum[k];
        gmu[k][d] = mu;
        outMu[k * DD + d] = mu;
    }
    __syncwarp();
    for (int c = lane; c < 512; c += 32) {
        int k = c >> 4, l = c & 15;
        float rs = grsum[k];
        float mu = gMuNum[d][k] / rs;
        gSiAi2[k][d][l] = (sums[warp][c] - mu * gG[k][l]) / rs;
    }
}

// ---------------- per-k M-step ----------------
__global__ void __launch_bounds__(256) mstep_kernel(const float* __restrict__ A,
                                                    float* __restrict__ outA,
                                                    float* __restrict__ outLogD,
                                                    float* __restrict__ outPI) {
    int k = blockIdx.x, t = threadIdx.x;
    int li = t >> 4, mi = t & 15;
    __shared__ float sS[16][16];
    __shared__ float sAs[16][16];
    float acc = 0.f;
    for (int d0 = 0; d0 < DD; d0 += 16) {
        __syncthreads();
        sAs[li][mi] = A[((size_t)k * DD + d0 + li) * LL + mi];
        sS [li][mi] = gSiAi2[k][d0 + li][mi];
        __syncthreads();
        #pragma unroll
        for (int dd = 0; dd < 16; ++dd) acc += sAs[dd][li] * sS[dd][mi];
    }
    __shared__ float sATS[16][16];
    __shared__ float siM[16][16];
    __syncthreads();
    sATS[li][mi] = acc;
    siM[li][mi] = gInvM[k][li][mi];
    __syncthreads();
    float Tv = 0.f;
    #pragma unroll
    for (int j = 0; j < 16; ++j) Tv += siM[li][j] * sATS[j][mi];
    __shared__ float aug[16][32];
    __shared__ float sfac[16];
    __shared__ int spiv;
    aug[li][mi]      = Tv + (li == mi ? gs2[k] : 0.f);
    aug[li][16 + mi] = (li == mi ? 1.f : 0.f);
    block_invert16(aug, nullptr, sfac, &spiv);
    __shared__ float sW2[16][16];
    sW2[li][mi] = aug[li][16 + mi];
    __syncthreads();
    float t1acc = 0.f;
    for (int d0 = 0; d0 < DD; d0 += 16) {
        __syncthreads();
        sS[li][mi] = gSiAi2[k][d0 + li][mi];
        __syncthreads();
        float an = 0.f, sim = 0.f;
        #pragma unroll
        for (int m = 0; m < 16; ++m) {
            float sv = sS[li][m];
            an  += sv * sW2[m][mi];
            sim += sv * siM[m][mi];
        }
        outA[((size_t)k * DD + d0 + li) * LL + mi] = an;
        t1acc += an * sim;
    }
    float msq = 0.f;
    for (int d = t; d < DD; d += 256) { float m = gmu[k][d]; msq += m * m; }
    __shared__ float sred[256];
    float t1   = block_reduce_sum(t1acc, sred);
    float msqs = block_reduce_sum(msq, sred);
    __shared__ float sld;
    if (t == 0) {
        float rs = grsum[k];
        float traceS = (grx2[k] - rs * msqs) / rs;
        float sig2 = (traceS - t1) / (float)DD;
        sld = logf(sig2);
        float tot = 0.f;
        for (int j = 0; j < KK; ++j) tot += grsum[j];
        outPI[k] = logf(grsum[k] / tot);
    }
    __syncthreads();
    float ldv = sld;
    for (int d = t; d < DD; d += 256) outLogD[k * DD + d] = ldv;
}

// ---------------- launch ----------------
extern "C" void kernel_launch(void* const* d_in, const int* in_sizes, int n_in,
                              void* d_out, int out_size) {
    const float* x   = (const float*)d_in[0];
    const float* MU  = (const float*)d_in[1];
    const float* A   = (const float*)d_in[2];
    const float* lD  = (const float*)d_in[3];
    const float* PIl = (const float*)d_in[4];
    float* out = (float*)d_out;
    float* outMu   = out;
    float* outA    = out + KK * DD;
    float* outLogD = out + KK * DD + KK * DD * LL;
    float* outPI   = out + KK * DD + KK * DD * LL + KK * DD;

    const int DSMEM = NSTAGE * STGSZ;   // 98304
    static int inited = 0;
    static cudaStream_t sSide1, sSide2;
    static cudaEvent_t evFork, evT, evS;
    if (!inited) {
        cudaFuncSetAttribute(mma_gemm_fused, cudaFuncAttributeMaxDynamicSharedMemorySize, DSMEM);
        cudaStreamCreateWithFlags(&sSide1, cudaStreamNonBlocking);
        cudaStreamCreateWithFlags(&sSide2, cudaStreamNonBlocking);
        cudaEventCreateWithFlags(&evFork, cudaEventDisableTiming);
        cudaEventCreateWithFlags(&evT, cudaEventDisableTiming);
        cudaEventCreateWithFlags(&evS, cudaEventDisableTiming);
        inited = 1;
    }

    __nv_bfloat16 *pXhi, *pXlo, *pXThi, *pXTlo, *pWThi, *pWTlo, *pM2Thi, *pM2Tlo;
    float *pCs, *pSiAiP, *pMuNum;
    cudaGetSymbolAddress((void**)&pXhi,   gXhi);
    cudaGetSymbolAddress((void**)&pXlo,   gXlo);
    cudaGetSymbolAddress((void**)&pXThi,  gXThi);
    cudaGetSymbolAddress((void**)&pXTlo,  gXTlo);
    cudaGetSymbolAddress((void**)&pWThi,  gWThi);
    cudaGetSymbolAddress((void**)&pWTlo,  gWTlo);
    cudaGetSymbolAddress((void**)&pM2Thi, gM2Thi);
    cudaGetSymbolAddress((void**)&pM2Tlo, gM2Tlo);
    cudaGetSymbolAddress((void**)&pCs,    gCs);
    cudaGetSymbolAddress((void**)&pSiAiP, gSiAiP);
    cudaGetSymbolAddress((void**)&pMuNum, gMuNum);

    // fork
    cudaEventRecord(evFork, 0);
    cudaStreamWaitEvent(sSide1, evFork, 0);
    cudaStreamWaitEvent(sSide2, evFork, 0);
    xprep_T<<<dim3(DD / 32, NN / 32), 256, 0, sSide1>>>(x);
    cudaEventRecord(evT, sSide1);
    setup_kernel<<<KK, 256, 0, sSide2>>>(MU, A, lD, PIl);
    cudaEventRecord(evS, sSide2);

    // main stream
    zero_kernel<<<128, 256>>>();
    xprep_straight<<<NN / 8, 256>>>(x);
    cudaStreamWaitEvent(0, evS, 0);
    mma_gemm_fused<<<dim3(NN / 128, 5, ZC), 256, DSMEM>>>(
        pXhi, pXlo, DD, pWThi, pWTlo, DD,
        pCs, WPAD, NN * WPAD, 32,
        pCs, WPAD, NN * WPAD, 0, 0,
        DD / ZC);
    estep_epilogue<<<NN / 8, 256>>>();
    tsplit_m2_kernel<<<dim3(M2W / 32, NN / 32), 256>>>();
    cudaStreamWaitEvent(0, evT, 0);
    mma_gemm_fused<<<dim3(DD / 128, 5, ZD), 256, DSMEM>>>(
        pXThi, pXTlo, NN, pM2Thi, pM2Tlo, NN,
        pSiAiP, ZD * 512, 512, 0,
        pMuNum, KK, 0, 512, 1,
        NN / ZD);
    finalize_kernel<<<DD / 8, 256>>>(outMu);
    mstep_kernel<<<KK, 256>>>(A, outA, outLogD, outPI);
}

// round 16
// speedup vs baseline: 1.0644x; 1.0644x over previous
#include <cuda_runtime.h>
#include <cuda_bf16.h>
#include <math.h>
#include <stdint.h>

#define NN 16384
#define DD 1024
#define KK 32
#define LL 16
#define WPAD 640
#define M2W 576
#define ZC 2
#define ZD 32
#define LOG2PI_F 1.8378770664093453f

// ---------------- device scratch ----------------
__device__ __align__(16) __nv_bfloat16 gXhi [NN][DD];
__device__ __align__(16) __nv_bfloat16 gXlo [NN][DD];
__device__ __align__(16) __nv_bfloat16 gXThi[DD][NN];
__device__ __align__(16) __nv_bfloat16 gXTlo[DD][NN];
__device__ __align__(16) __nv_bfloat16 gWThi[WPAD][DD];
__device__ __align__(16) __nv_bfloat16 gWTlo[WPAD][DD];
__device__ __align__(16) __nv_bfloat16 gM2Thi[M2W][NN];
__device__ __align__(16) __nv_bfloat16 gM2Tlo[M2W][NN];
__device__ float gCs[ZC][NN][WPAD];    // ZC K-slabs of [cross(32) | P(512)]
__device__ float gM2[NN][M2W];         // [rP(512) | r(32) | rx2(32)]
__device__ float gX2[NN];
__device__ float gSiAiP[DD][ZD][512];  // ZD k-split slabs of x^T(rP)
__device__ float gMuNum[DD][KK];       // x^T r (atomic)
__device__ float gSiAi2[KK][DD][LL];
__device__ float gmu[KK][DD];
__device__ float giL  [KK][LL][LL];
__device__ float gInvM[KK][LL][LL];
__device__ float gbmu [KK][LL];
__device__ float gG   [KK][LL];
__device__ float gmuSq[KK];
__device__ float giD [KK];
__device__ float gck[KK];
__device__ float gs2[KK];
__device__ float grsum[KK];
__device__ float grx2[KK];

// ---------------- helpers ----------------
__device__ __forceinline__ uint32_t s2u(const void* p) {
    uint32_t a;
    asm("{ .reg .u64 t; cvta.to.shared.u64 t, %1; cvt.u32.u64 %0, t; }" : "=r"(a) : "l"(p));
    return a;
}
__device__ __forceinline__ void ldm4(uint32_t* r, uint32_t addr) {
    asm volatile("ldmatrix.sync.aligned.m8n8.x4.shared.b16 {%0,%1,%2,%3}, [%4];"
                 : "=r"(r[0]), "=r"(r[1]), "=r"(r[2]), "=r"(r[3]) : "r"(addr));
}
__device__ __forceinline__ void mma16816(float* c, const uint32_t* a, uint32_t b0, uint32_t b1) {
    asm volatile(
        "mma.sync.aligned.m16n8k16.row.col.f32.bf16.bf16.f32 "
        "{%0,%1,%2,%3}, {%4,%5,%6,%7}, {%8,%9}, {%0,%1,%2,%3};"
        : "+f"(c[0]), "+f"(c[1]), "+f"(c[2]), "+f"(c[3])
        : "r"(a[0]), "r"(a[1]), "r"(a[2]), "r"(a[3]), "r"(b0), "r"(b1));
}
__device__ __forceinline__ void cpasync16(uint32_t smem, const void* g) {
    asm volatile("cp.async.cg.shared.global [%0], [%1], 16;" :: "r"(smem), "l"(g) : "memory");
}
#define CP_COMMIT() asm volatile("cp.async.commit_group;" ::: "memory")
#define CP_WAIT2()  asm volatile("cp.async.wait_group 2;" ::: "memory")

__device__ __forceinline__ float block_reduce_sum(float v, float* sbuf) {
    int t = threadIdx.x;
    sbuf[t] = v; __syncthreads();
    for (int s = 128; s > 0; s >>= 1) {
        if (t < s) sbuf[t] += sbuf[t + s];
        __syncthreads();
    }
    float r = sbuf[0];
    __syncthreads();
    return r;
}
__device__ void block_invert16(float aug[16][32], float* slogdet, float* sfac, int* spiv) {
    int t = threadIdx.x;
    int r = t >> 4, c = t & 15;
    for (int p = 0; p < 16; ++p) {
        __syncthreads();
        if (t < 32) {
            float v = (t < 16 && t >= p) ? fabsf(aug[t][p]) : -1.f;
            int idx = t;
            #pragma unroll
            for (int off = 8; off > 0; off >>= 1) {
                float ov = __shfl_xor_sync(0xffffffffu, v, off);
                int oi = __shfl_xor_sync(0xffffffffu, idx, off);
                if (ov > v) { v = ov; idx = oi; }
            }
            if (t == 0) {
                *spiv = idx;
                if (slogdet) *slogdet += logf(fmaxf(v, 1e-30f));
            }
        }
        __syncthreads();
        int pr = *spiv;
        if (pr != p && t < 32) { float tmp = aug[p][t]; aug[p][t] = aug[pr][t]; aug[pr][t] = tmp; }
        __syncthreads();
        if (t < 32) {
            float val = aug[p][t];
            float pv  = aug[p][p];
            __syncwarp();
            aug[p][t] = val / pv;
        }
        __syncthreads();
        if (c == 0) sfac[r] = aug[r][p];
        __syncthreads();
        if (r != p) {
            float f = sfac[r];
            aug[r][c]      -= f * aug[p][c];
            aug[r][c + 16] -= f * aug[p][c + 16];
        }
    }
    __syncthreads();
}

// ---------------- kernel 0: zero scratch (side stream) ----------------
__global__ void zero_kernel() {
    int i0 = blockIdx.x * 256 + threadIdx.x;
    int str = gridDim.x * 256;
    for (int i = i0; i < DD * KK; i += str) (&gMuNum[0][0])[i] = 0.f;
    if (i0 < KK) { grsum[i0] = 0.f; grx2[i0] = 0.f; }
    if (i0 < KK * LL) (&gG[0][0])[i0] = 0.f;
}

// ---------------- straight split + x2 (critical path) ----------------
__global__ void __launch_bounds__(256) xprep_straight(const float* __restrict__ x) {
    int warp = threadIdx.x >> 5, lane = threadIdx.x & 31;
    int n = blockIdx.x * 8 + warp;
    const float4* xr = (const float4*)(x + (size_t)n * DD);
    float s = 0.f;
    #pragma unroll
    for (int c = lane; c < 256; c += 32) {
        float4 v = xr[c];
        s += v.x * v.x + v.y * v.y + v.z * v.z + v.w * v.w;
        __nv_bfloat16 h0 = __float2bfloat16(v.x), h1 = __float2bfloat16(v.y);
        __nv_bfloat16 h2 = __float2bfloat16(v.z), h3 = __float2bfloat16(v.w);
        ushort4 ph, pl;
        ph.x = __bfloat16_as_ushort(h0); ph.y = __bfloat16_as_ushort(h1);
        ph.z = __bfloat16_as_ushort(h2); ph.w = __bfloat16_as_ushort(h3);
        pl.x = __bfloat16_as_ushort(__float2bfloat16(v.x - __bfloat162float(h0)));
        pl.y = __bfloat16_as_ushort(__float2bfloat16(v.y - __bfloat162float(h1)));
        pl.z = __bfloat16_as_ushort(__float2bfloat16(v.z - __bfloat162float(h2)));
        pl.w = __bfloat16_as_ushort(__float2bfloat16(v.w - __bfloat162float(h3)));
        *(ushort4*)(&gXhi[n][c * 4]) = ph;
        *(ushort4*)(&gXlo[n][c * 4]) = pl;
    }
    #pragma unroll
    for (int off = 16; off > 0; off >>= 1) s += __shfl_xor_sync(0xffffffffu, s, off);
    if (lane == 0) gX2[n] = s;
}

// ---------------- transposed split (side stream 1) ----------------
__global__ void __launch_bounds__(256) xprep_T(const float* __restrict__ x) {
    __shared__ float tile[32][33];
    int t = threadIdx.x;
    int tx8 = t & 7, ty = t >> 3;
    int c0 = blockIdx.x * 32, r0 = blockIdx.y * 32;
    float4 v = *(const float4*)(x + (size_t)(r0 + ty) * DD + c0 + tx8 * 4);
    tile[ty][tx8 * 4 + 0] = v.x;
    tile[ty][tx8 * 4 + 1] = v.y;
    tile[ty][tx8 * 4 + 2] = v.z;
    tile[ty][tx8 * 4 + 3] = v.w;
    __syncthreads();
    int cc = t >> 3, rq = (t & 7) * 4;
    float w0 = tile[rq + 0][cc], w1 = tile[rq + 1][cc];
    float w2 = tile[rq + 2][cc], w3 = tile[rq + 3][cc];
    __nv_bfloat16 g0 = __float2bfloat16(w0), g1 = __float2bfloat16(w1);
    __nv_bfloat16 g2 = __float2bfloat16(w2), g3 = __float2bfloat16(w3);
    ushort4 qh, ql;
    qh.x = __bfloat16_as_ushort(g0); qh.y = __bfloat16_as_ushort(g1);
    qh.z = __bfloat16_as_ushort(g2); qh.w = __bfloat16_as_ushort(g3);
    ql.x = __bfloat16_as_ushort(__float2bfloat16(w0 - __bfloat162float(g0)));
    ql.y = __bfloat16_as_ushort(__float2bfloat16(w1 - __bfloat162float(g1)));
    ql.z = __bfloat16_as_ushort(__float2bfloat16(w2 - __bfloat162float(g2)));
    ql.w = __bfloat16_as_ushort(__float2bfloat16(w3 - __bfloat162float(g3)));
    *(ushort4*)(&gXThi[c0 + cc][r0 + rq]) = qh;
    *(ushort4*)(&gXTlo[c0 + cc][r0 + rq]) = ql;
}

// ---------------- per-k setup (side stream 2), 64-row-chunked ----------------
__global__ void setup_kernel(const float* __restrict__ MU, const float* __restrict__ A,
                             const float* __restrict__ log_D, const float* __restrict__ PI_logits) {
    int k = blockIdx.x, t = threadIdx.x;
    __shared__ float sred[256];
    __shared__ float sPIk;
    if (t == 0) {
        float mx = -1e30f;
        for (int j = 0; j < KK; ++j) mx = fmaxf(mx, PI_logits[j]);
        float s = 0.f;
        for (int j = 0; j < KK; ++j) s += expf(PI_logits[j] - mx);
        sPIk = expf(PI_logits[k] - mx) / s;
    }
    float ld0 = log_D[(size_t)k * DD];
    float iD = expf(-ld0);
    float s2 = expf(ld0);
    float muSqAcc = 0.f;
    for (int d = t; d < DD; d += 256) {
        float mu = MU[(size_t)k * DD + d];
        __nv_bfloat16 h = __float2bfloat16(mu);
        gWThi[k][d] = h;
        gWTlo[k][d] = __float2bfloat16(mu - __bfloat162float(h));
        muSqAcc += mu * mu;
    }
    __shared__ float sA[64][17];
    int li = t >> 4, mi = t & 15;
    float ATAacc = 0.f, bmuAcc = 0.f;
    const int lw = t >> 4;
    const int dq = (t & 15) * 4;
    for (int c0 = 0; c0 < DD; c0 += 64) {
        __syncthreads();
        {
            int row = t >> 2, q = (t & 3) * 4;
            float4 a4 = *(const float4*)(A + ((size_t)k * DD + c0 + row) * LL + q);
            sA[row][q + 0] = a4.x;
            sA[row][q + 1] = a4.y;
            sA[row][q + 2] = a4.z;
            sA[row][q + 3] = a4.w;
        }
        __syncthreads();
        {
            float4 m4 = *(const float4*)(MU + (size_t)k * DD + c0 + dq);
            float a0 = sA[dq + 0][lw], a1 = sA[dq + 1][lw];
            float a2 = sA[dq + 2][lw], a3 = sA[dq + 3][lw];
            bmuAcc += m4.x * a0 + m4.y * a1 + m4.z * a2 + m4.w * a3;
            __nv_bfloat16 h0 = __float2bfloat16(a0), h1 = __float2bfloat16(a1);
            __nv_bfloat16 h2 = __float2bfloat16(a2), h3 = __float2bfloat16(a3);
            ushort4 ph, pl;
            ph.x = __bfloat16_as_ushort(h0); ph.y = __bfloat16_as_ushort(h1);
            ph.z = __bfloat16_as_ushort(h2); ph.w = __bfloat16_as_ushort(h3);
            pl.x = __bfloat16_as_ushort(__float2bfloat16(a0 - __bfloat162float(h0)));
            pl.y = __bfloat16_as_ushort(__float2bfloat16(a1 - __bfloat162float(h1)));
            pl.z = __bfloat16_as_ushort(__float2bfloat16(a2 - __bfloat162float(h2)));
            pl.w = __bfloat16_as_ushort(__float2bfloat16(a3 - __bfloat162float(h3)));
            *(ushort4*)(&gWThi[32 + k * 16 + lw][c0 + dq]) = ph;
            *(ushort4*)(&gWTlo[32 + k * 16 + lw][c0 + dq]) = pl;
        }
        #pragma unroll
        for (int dd = 0; dd < 64; ++dd) ATAacc += sA[dd][li] * sA[dd][mi];
    }
    float muSqK = block_reduce_sum(muSqAcc, sred);
    __shared__ float sbm[16][17];
    sbm[lw][t & 15] = bmuAcc;
    __syncthreads();
    if (t < 16) {
        float s = 0.f;
        for (int g = 0; g < 16; ++g) s += sbm[t][g];
        gbmu[k][t] = s;
    }
    __shared__ float aug[16][32];
    __shared__ float sfac[16];
    __shared__ int spiv;
    __shared__ float slogdet;
    if (t == 0) slogdet = 0.f;
    __syncthreads();
    aug[li][mi]      = iD * ATAacc + (li == mi ? 1.f : 0.f);
    aug[li][16 + mi] = (li == mi ? 1.f : 0.f);
    block_invert16(aug, &slogdet, sfac, &spiv);
    giL[k][li][mi] = aug[li][16 + mi];
    float logdetL = slogdet;
    __syncthreads();
    aug[li][mi]      = ATAacc + (li == mi ? s2 : 0.f);
    aug[li][16 + mi] = (li == mi ? 1.f : 0.f);
    block_invert16(aug, nullptr, sfac, &spiv);
    gInvM[k][li][mi] = aug[li][16 + mi];
    if (t == 0) {
        gmuSq[k] = muSqK;
        giD[k] = iD;
        gs2[k] = s2;
        gck[k] = sPIk - 0.5f * ((float)DD * LOG2PI_F + logdetL + (float)DD * ld0);
    }
}

// ---------------- fused mma GEMM: fat 128x128 tiles (y<4) + skinny 128x32 (y==4) ----------------
#define SR16 24
#define STG_AHI 0
#define STG_ALO 6144
#define STG_BHI 12288
#define STG_BLO 18432
#define STGSZ   24576
#define NSTAGE  4

__global__ void __launch_bounds__(256, 2) mma_gemm_fused(
    const __nv_bfloat16* __restrict__ Ahi, const __nv_bfloat16* __restrict__ Alo, int lda,
    const __nv_bfloat16* __restrict__ Bhi, const __nv_bfloat16* __restrict__ Blo, int ldb,
    float* __restrict__ C, int ldc, int zstride, int nOffFat,
    float* __restrict__ Cs, int ldcs, int zstrideS, int bOffS, int atomicS,
    int kLen)
{
    extern __shared__ __align__(128) char ds[];
    const uint32_t sbase = s2u(ds);
    const int t = threadIdx.x, lane = t & 31, w = t >> 5;
    const int m0 = blockIdx.x * 128;
    const int kBeg = blockIdx.z * kLen;
    const int nCh = kLen >> 4;

    if (blockIdx.y < 4) {
        const int wm = w & 1, wn = w >> 1;
        const int n0 = nOffFat + blockIdx.y * 128;
        float* Cf = C + (size_t)blockIdx.z * zstride;

        const int row = t >> 1, half = (t & 1) * 8;
        const size_t gA = (size_t)(m0 + row) * lda + kBeg + half;
        const size_t gB = (size_t)(n0 + row) * ldb + kBeg + half;
        const uint32_t soff = (uint32_t)(row * SR16 + half) * 2;
        const int aoff0 = ((wm * 64 + (lane & 15)) * SR16 + ((lane >> 4) << 3)) * 2;
        const int boff0 = ((wn * 32 + (lane & 15)) * SR16 + ((lane >> 4) << 3)) * 2;

        float acc[4][4][4] = {};

        #pragma unroll
        for (int st = 0; st < NSTAGE - 1; ++st) {
            uint32_t sb = sbase + st * STGSZ;
            int kk = st * 16;
            cpasync16(sb + STG_AHI + soff, Ahi + gA + kk);
            cpasync16(sb + STG_ALO + soff, Alo + gA + kk);
            cpasync16(sb + STG_BHI + soff, Bhi + gB + kk);
            cpasync16(sb + STG_BLO + soff, Blo + gB + kk);
            CP_COMMIT();
        }
        for (int ch = 0; ch < nCh; ++ch) {
            CP_WAIT2();
            __syncthreads();
            const uint32_t sb = sbase + (ch & 3) * STGSZ;
            uint32_t ah[4][4], al[4][4], bh[2][4], bl[2][4];
            #pragma unroll
            for (int p = 0; p < 2; ++p) {
                ldm4(bh[p], sb + STG_BHI + boff0 + p * 16 * SR16 * 2);
                ldm4(bl[p], sb + STG_BLO + boff0 + p * 16 * SR16 * 2);
            }
            #pragma unroll
            for (int mf = 0; mf < 4; ++mf) {
                ldm4(ah[mf], sb + STG_AHI + aoff0 + mf * 16 * SR16 * 2);
                ldm4(al[mf], sb + STG_ALO + aoff0 + mf * 16 * SR16 * 2);
            }
            #pragma unroll
            for (int mf = 0; mf < 4; ++mf)
                #pragma unroll
                for (int nf = 0; nf < 4; ++nf) {
                    int p = nf >> 1, o = nf & 1;
                    mma16816(acc[mf][nf], ah[mf], bh[p][o], bh[p][2 + o]);
                }
            #pragma unroll
            for (int mf = 0; mf < 4; ++mf)
                #pragma unroll
                for (int nf = 0; nf < 4; ++nf) {
                    int p = nf >> 1, o = nf & 1;
                    mma16816(acc[mf][nf], ah[mf], bl[p][o], bl[p][2 + o]);
                }
            #pragma unroll
            for (int mf = 0; mf < 4; ++mf)
                #pragma unroll
                for (int nf = 0; nf < 4; ++nf) {
                    int p = nf >> 1, o = nf & 1;
                    mma16816(acc[mf][nf], al[mf], bh[p][o], bh[p][2 + o]);
                }
            int st = ch + NSTAGE - 1;
            if (st < nCh) {
                uint32_t sn = sbase + (st & 3) * STGSZ;
                int kk = st * 16;
                cpasync16(sn + STG_AHI + soff, Ahi + gA + kk);
                cpasync16(sn + STG_ALO + soff, Alo + gA + kk);
                cpasync16(sn + STG_BHI + soff, Bhi + gB + kk);
                cpasync16(sn + STG_BLO + soff, Blo + gB + kk);
            }
            CP_COMMIT();
        }
        const int gid = lane >> 2, tid = lane & 3;
        #pragma unroll
        for (int mf = 0; mf < 4; ++mf) {
            #pragma unroll
            for (int nf = 0; nf < 4; ++nf) {
                int rr = m0 + wm * 64 + mf * 16 + gid;
                int col = n0 + wn * 32 + nf * 8 + tid * 2;
                float* c0 = Cf + (size_t)rr * ldc + col;
                float* c1 = Cf + (size_t)(rr + 8) * ldc + col;
                *(float2*)c0 = make_float2(acc[mf][nf][0], acc[mf][nf][1]);
                *(float2*)c1 = make_float2(acc[mf][nf][2], acc[mf][nf][3]);
            }
        }
    } else {
        const int wm = w >> 1, wn = w & 1;
        float* Csf = Cs + (size_t)blockIdx.z * zstrideS;
        const int row = t >> 1, half = (t & 1) * 8;
        const size_t gA = (size_t)(m0 + row) * lda + kBeg + half;
        const uint32_t soffA = (uint32_t)(row * SR16 + half) * 2;
        const int rowB = (t & 63) >> 1;
        const size_t gB = (size_t)(bOffS + rowB) * ldb + kBeg + half;
        const uint32_t soffB = (uint32_t)(rowB * SR16 + half) * 2;
        const bool doB = (t < 64);
        const int aoff0 = ((wm * 32 + (lane & 15)) * SR16 + ((lane >> 4) << 3)) * 2;
        const int boff0 = ((wn * 16 + (lane & 15)) * SR16 + ((lane >> 4) << 3)) * 2;

        float acc[2][2][4] = {};

        #pragma unroll
        for (int st = 0; st < NSTAGE - 1; ++st) {
            uint32_t sb = sbase + st * STGSZ;
            int kk = st * 16;
            cpasync16(sb + STG_AHI + soffA, Ahi + gA + kk);
            cpasync16(sb + STG_ALO + soffA, Alo + gA + kk);
            if (doB) {
                cpasync16(sb + STG_BHI + soffB, Bhi + gB + kk);
                cpasync16(sb + STG_BLO + soffB, Blo + gB + kk);
            }
            CP_COMMIT();
        }
        for (int ch = 0; ch < nCh; ++ch) {
            CP_WAIT2();
            __syncthreads();
            const uint32_t sb = sbase + (ch & 3) * STGSZ;
            uint32_t ah[2][4], al[2][4], bh[4], bl[4];
            ldm4(bh, sb + STG_BHI + boff0);
            ldm4(bl, sb + STG_BLO + boff0);
            #pragma unroll
            for (int mf = 0; mf < 2; ++mf) {
                ldm4(ah[mf], sb + STG_AHI + aoff0 + mf * 16 * SR16 * 2);
                ldm4(al[mf], sb + STG_ALO + aoff0 + mf * 16 * SR16 * 2);
            }
            #pragma unroll
            for (int mf = 0; mf < 2; ++mf)
                #pragma unroll
                for (int nf = 0; nf < 2; ++nf)
                    mma16816(acc[mf][nf], ah[mf], bh[nf], bh[2 + nf]);
            #pragma unroll
            for (int mf = 0; mf < 2; ++mf)
                #pragma unroll
                for (int nf = 0; nf < 2; ++nf)
                    mma16816(acc[mf][nf], ah[mf], bl[nf], bl[2 + nf]);
            #pragma unroll
            for (int mf = 0; mf < 2; ++mf)
                #pragma unroll
                for (int nf = 0; nf < 2; ++nf)
                    mma16816(acc[mf][nf], al[mf], bh[nf], bh[2 + nf]);
            int st = ch + NSTAGE - 1;
            if (st < nCh) {
                uint32_t sn = sbase + (st & 3) * STGSZ;
                int kk = st * 16;
                cpasync16(sn + STG_AHI + soffA, Ahi + gA + kk);
                cpasync16(sn + STG_ALO + soffA, Alo + gA + kk);
                if (doB) {
                    cpasync16(sn + STG_BHI + soffB, Bhi + gB + kk);
                    cpasync16(sn + STG_BLO + soffB, Blo + gB + kk);
                }
            }
            CP_COMMIT();
        }
        const int gid = lane >> 2, tid = lane & 3;
        #pragma unroll
        for (int mf = 0; mf < 2; ++mf) {
            #pragma unroll
            for (int nf = 0; nf < 2; ++nf) {
                int rr = m0 + wm * 32 + mf * 16 + gid;
                int col = wn * 16 + nf * 8 + tid * 2;
                float* c0 = Csf + (size_t)rr * ldcs + col;
                float* c1 = Csf + (size_t)(rr + 8) * ldcs + col;
                if (atomicS) {
                    atomicAdd(c0,     acc[mf][nf][0]);
                    atomicAdd(c0 + 1, acc[mf][nf][1]);
                    atomicAdd(c1,     acc[mf][nf][2]);
                    atomicAdd(c1 + 1, acc[mf][nf][3]);
                } else {
                    *(float2*)c0 = make_float2(acc[mf][nf][0], acc[mf][nf][1]);
                    *(float2*)c1 = make_float2(acc[mf][nf][2], acc[mf][nf][3]);
                }
            }
        }
    }
}

// ---------------- E-step epilogue (sums the ZC gC slabs) ----------------
__global__ void __launch_bounds__(256) estep_epilogue() {
    __shared__ float siLs[KK * 272];
    __shared__ float sbmu_[KK][LL];
    __shared__ float smuSq_[KK];
    __shared__ float siD_[KK];
    __shared__ float sck_[KK];
    __shared__ float sll[8][32];
    int t = threadIdx.x;
    for (int idx = t; idx < KK * 256; idx += 256) {
        int kk = idx >> 8, rem = idx & 255;
        siLs[kk * 272 + (rem >> 4) * 17 + (rem & 15)] = (&giL[0][0][0])[idx];
    }
    for (int idx = t; idx < KK * LL; idx += 256) (&sbmu_[0][0])[idx] = (&gbmu[0][0])[idx];
    if (t < KK) { smuSq_[t] = gmuSq[t]; sck_[t] = gck[t]; siD_[t] = giD[t]; }
    __syncthreads();

    int warp = t >> 5, lane = t & 31;
    int n = blockIdx.x * 8 + warp;
    const float* C0 = &gCs[0][n][0];
    const float* C1 = &gCs[1][n][0];
    float x2 = gX2[n];
    #pragma unroll 1
    for (int it = 0; it < 16; ++it) {
        int k = it * 2 + (lane >> 4);
        int gl = lane & 15;
        int jj = 32 + k * 16 + gl;
        float yv = C0[jj] + C1[jj] - sbmu_[k][gl];
        float z = 0.f;
        const float* ilr = &siLs[k * 272 + gl * 17];
        #pragma unroll
        for (int m = 0; m < 16; ++m) {
            float ym = __shfl_sync(0xffffffffu, yv, (lane & 16) | m);
            z += ilr[m] * ym;
        }
        float t2 = z * yv;
        #pragma unroll
        for (int off = 8; off > 0; off >>= 1) t2 += __shfl_xor_sync(0xffffffffu, t2, off);
        if (gl == 0) {
            float iD = siD_[k];
            float cross = C0[k] + C1[k];
            float term1 = iD * (x2 - 2.f * cross + smuSq_[k]);
            sll[warp][k] = sck_[k] - 0.5f * term1 + 0.5f * iD * iD * t2;
        }
    }
    __syncwarp();
    float llk = sll[warp][lane];
    float mx = llk;
    #pragma unroll
    for (int off = 16; off > 0; off >>= 1) mx = fmaxf(mx, __shfl_xor_sync(0xffffffffu, mx, off));
    float e = expf(llk - mx);
    float s = e;
    #pragma unroll
    for (int off = 16; off > 0; off >>= 1) s += __shfl_xor_sync(0xffffffffu, s, off);
    float r = e / s;
    float* Mrow = &gM2[n][0];
    Mrow[512 + lane] = r;
    Mrow[544 + lane] = r * x2;
    #pragma unroll
    for (int it = 0; it < 16; ++it) {
        int j = it * 32 + lane;
        float rk = __shfl_sync(0xffffffffu, r, j >> 4);
        Mrow[j] = rk * (C0[32 + j] + C1[32 + j]);
    }
}

// ---------------- transpose-split M2 + fused column sums ----------------
__global__ void __launch_bounds__(256) tsplit_m2_kernel() {
    __shared__ float tile[32][33];
    int t = threadIdx.x;
    int tx = t & 31, ty = t >> 5;
    int c0 = blockIdx.x * 32;
    int r0 = blockIdx.y * 32;
    #pragma unroll
    for (int j = 0; j < 32; j += 8)
        tile[ty + j][tx] = gM2[r0 + ty + j][c0 + tx];
    __syncthreads();
    #pragma unroll
    for (int j = 0; j < 32; j += 8) {
        int wcol = c0 + ty + j;
        int h = r0 + tx;
        float v = tile[tx][ty + j];
        __nv_bfloat16 hi = __float2bfloat16(v);
        gM2Thi[wcol][h] = hi;
        gM2Tlo[wcol][h] = __float2bfloat16(v - __bfloat162float(hi));
    }
    if (t < 32) {
        int col = c0 + t;
        float s = 0.f;
        #pragma unroll
        for (int rr = 0; rr < 32; ++rr) s += tile[rr][t];
        if (col < 512)      atomicAdd(&gG[0][0] + col, s);
        else if (col < 544) atomicAdd(&grsum[col - 512], s);
        else                atomicAdd(&grx2[col - 544], s);
    }
}

// ---------------- finalize: sum ZD slabs, mu + SiAi ----------------
__global__ void __launch_bounds__(256) finalize_kernel(float* __restrict__ outMu) {
    __shared__ float sums[8][512];
    int t = threadIdx.x, warp = t >> 5, lane = t & 31;
    int d = blockIdx.x * 8 + warp;
    const float* base = &gSiAiP[d][0][0];
    for (int c = lane; c < 512; c += 32) {
        float s = 0.f;
        #pragma unroll
        for (int j = 0; j < ZD; ++j) s += base[j * 512 + c];
        sums[warp][c] = s;
    }
    {
        int k = lane;
        float mu = gMuNum[d][k] / grsum[k];
        gmu[k][d] = mu;
        outMu[k * DD + d] = mu;
    }
    __syncwarp();
    for (int c = lane; c < 512; c += 32) {
        int k = c >> 4, l = c & 15;
        float rs = grsum[k];
        float mu = gMuNum[d][k] / rs;
        gSiAi2[k][d][l] = (sums[warp][c] - mu * gG[k][l]) / rs;
    }
}

// ---------------- per-k M-step ----------------
__global__ void __launch_bounds__(256) mstep_kernel(const float* __restrict__ A,
                                                    float* __restrict__ outA,
                                                    float* __restrict__ outLogD,
                                                    float* __restrict__ outPI) {
    int k = blockIdx.x, t = threadIdx.x;
    int li = t >> 4, mi = t & 15;
    __shared__ float sS[16][16];
    __shared__ float sAs[16][16];
    float acc = 0.f;
    for (int d0 = 0; d0 < DD; d0 += 16) {
        __syncthreads();
        sAs[li][mi] = A[((size_t)k * DD + d0 + li) * LL + mi];
        sS [li][mi] = gSiAi2[k][d0 + li][mi];
        __syncthreads();
        #pragma unroll
        for (int dd = 0; dd < 16; ++dd) acc += sAs[dd][li] * sS[dd][mi];
    }
    __shared__ float sATS[16][16];
    __shared__ float siM[16][16];
    __syncthreads();
    sATS[li][mi] = acc;
    siM[li][mi] = gInvM[k][li][mi];
    __syncthreads();
    float Tv = 0.f;
    #pragma unroll
    for (int j = 0; j < 16; ++j) Tv += siM[li][j] * sATS[j][mi];
    __shared__ float aug[16][32];
    __shared__ float sfac[16];
    __shared__ int spiv;
    aug[li][mi]      = Tv + (li == mi ? gs2[k] : 0.f);
    aug[li][16 + mi] = (li == mi ? 1.f : 0.f);
    block_invert16(aug, nullptr, sfac, &spiv);
    __shared__ float sW2[16][16];
    sW2[li][mi] = aug[li][16 + mi];
    __syncthreads();
    float t1acc = 0.f;
    for (int d0 = 0; d0 < DD; d0 += 16) {
        __syncthreads();
        sS[li][mi] = gSiAi2[k][d0 + li][mi];
        __syncthreads();
        float an = 0.f, sim = 0.f;
        #pragma unroll
        for (int m = 0; m < 16; ++m) {
            float sv = sS[li][m];
            an  += sv * sW2[m][mi];
            sim += sv * siM[m][mi];
        }
        outA[((size_t)k * DD + d0 + li) * LL + mi] = an;
        t1acc += an * sim;
    }
    float msq = 0.f;
    for (int d = t; d < DD; d += 256) { float m = gmu[k][d]; msq += m * m; }
    __shared__ float sred[256];
    float t1   = block_reduce_sum(t1acc, sred);
    float msqs = block_reduce_sum(msq, sred);
    __shared__ float sld;
    if (t == 0) {
        float rs = grsum[k];
        float traceS = (grx2[k] - rs * msqs) / rs;
        float sig2 = (traceS - t1) / (float)DD;
        sld = logf(sig2);
        float tot = 0.f;
        for (int j = 0; j < KK; ++j) tot += grsum[j];
        outPI[k] = logf(grsum[k] / tot);
    }
    __syncthreads();
    float ldv = sld;
    for (int d = t; d < DD; d += 256) outLogD[k * DD + d] = ldv;
}

// ---------------- launch ----------------
extern "C" void kernel_launch(void* const* d_in, const int* in_sizes, int n_in,
                              void* d_out, int out_size) {
    const float* x   = (const float*)d_in[0];
    const float* MU  = (const float*)d_in[1];
    const float* A   = (const float*)d_in[2];
    const float* lD  = (const float*)d_in[3];
    const float* PIl = (const float*)d_in[4];
    float* out = (float*)d_out;
    float* outMu   = out;
    float* outA    = out + KK * DD;
    float* outLogD = out + KK * DD + KK * DD * LL;
    float* outPI   = out + KK * DD + KK * DD * LL + KK * DD;

    const int DSMEM = NSTAGE * STGSZ;   // 98304
    static int inited = 0;
    static cudaStream_t sSide1, sSide2;
    static cudaEvent_t evFork, evT, evS;
    if (!inited) {
        cudaFuncSetAttribute(mma_gemm_fused, cudaFuncAttributeMaxDynamicSharedMemorySize, DSMEM);
        cudaStreamCreateWithFlags(&sSide1, cudaStreamNonBlocking);
        cudaStreamCreateWithFlags(&sSide2, cudaStreamNonBlocking);
        cudaEventCreateWithFlags(&evFork, cudaEventDisableTiming);
        cudaEventCreateWithFlags(&evT, cudaEventDisableTiming);
        cudaEventCreateWithFlags(&evS, cudaEventDisableTiming);
        inited = 1;
    }

    __nv_bfloat16 *pXhi, *pXlo, *pXThi, *pXTlo, *pWThi, *pWTlo, *pM2Thi, *pM2Tlo;
    float *pCs, *pSiAiP, *pMuNum;
    cudaGetSymbolAddress((void**)&pXhi,   gXhi);
    cudaGetSymbolAddress((void**)&pXlo,   gXlo);
    cudaGetSymbolAddress((void**)&pXThi,  gXThi);
    cudaGetSymbolAddress((void**)&pXTlo,  gXTlo);
    cudaGetSymbolAddress((void**)&pWThi,  gWThi);
    cudaGetSymbolAddress((void**)&pWTlo,  gWTlo);
    cudaGetSymbolAddress((void**)&pM2Thi, gM2Thi);
    cudaGetSymbolAddress((void**)&pM2Tlo, gM2Tlo);
    cudaGetSymbolAddress((void**)&pCs,    gCs);
    cudaGetSymbolAddress((void**)&pSiAiP, gSiAiP);
    cudaGetSymbolAddress((void**)&pMuNum, gMuNum);

    // fork
    cudaEventRecord(evFork, 0);
    cudaStreamWaitEvent(sSide1, evFork, 0);
    cudaStreamWaitEvent(sSide2, evFork, 0);
    xprep_T<<<dim3(DD / 32, NN / 32), 256, 0, sSide1>>>(x);
    cudaEventRecord(evT, sSide1);
    zero_kernel<<<128, 256, 0, sSide2>>>();
    setup_kernel<<<KK, 256, 0, sSide2>>>(MU, A, lD, PIl);
    cudaEventRecord(evS, sSide2);

    // main stream
    xprep_straight<<<NN / 8, 256>>>(x);
    cudaStreamWaitEvent(0, evS, 0);
    mma_gemm_fused<<<dim3(NN / 128, 5, ZC), 256, DSMEM>>>(
        pXhi, pXlo, DD, pWThi, pWTlo, DD,
        pCs, WPAD, NN * WPAD, 32,
        pCs, WPAD, NN * WPAD, 0, 0,
        DD / ZC);
    estep_epilogue<<<NN / 8, 256>>>();
    tsplit_m2_kernel<<<dim3(M2W / 32, NN / 32), 256>>>();
    cudaStreamWaitEvent(0, evT, 0);
    mma_gemm_fused<<<dim3(DD / 128, 5, ZD), 256, DSMEM>>>(
        pXThi, pXTlo, NN, pM2Thi, pM2Tlo, NN,
        pSiAiP, ZD * 512, 512, 0,
        pMuNum, KK, 0, 512, 1,
        NN / ZD);
    finalize_kernel<<<DD / 8, 256>>>(outMu);
    mstep_kernel<<<KK, 256>>>(A, outA, outLogD, outPI);
}

// round 17
// speedup vs baseline: 1.1260x; 1.0578x over previous
#include <cuda_runtime.h>
#include <cuda_bf16.h>
#include <math.h>
#include <stdint.h>

#define NN 16384
#define DD 1024
#define KK 32
#define LL 16
#define WPAD 640
#define M2W 576
#define ZC 2
#define ZD 32
#define LOG2PI_F 1.8378770664093453f

// ---------------- device scratch ----------------
__device__ __align__(16) __nv_bfloat16 gXhi [NN][DD];
__device__ __align__(16) __nv_bfloat16 gXlo [NN][DD];
__device__ __align__(16) __nv_bfloat16 gXThi[DD][NN];
__device__ __align__(16) __nv_bfloat16 gXTlo[DD][NN];
__device__ __align__(16) __nv_bfloat16 gWThi[WPAD][DD];
__device__ __align__(16) __nv_bfloat16 gWTlo[WPAD][DD];
__device__ __align__(16) __nv_bfloat16 gM2Thi[M2W][NN];
__device__ __align__(16) __nv_bfloat16 gM2Tlo[M2W][NN];
__device__ float gCs[ZC][NN][WPAD];
__device__ float gM2[NN][M2W];
__device__ float gX2[NN];
__device__ float gSiAiP[DD][ZD][512];
__device__ float gMuNum[DD][KK];
__device__ float gSiAi2[KK][DD][LL];
__device__ float gmu[KK][DD];
__device__ float giL  [KK][LL][LL];
__device__ float gInvM[KK][LL][LL];
__device__ float gbmu [KK][LL];
__device__ float gG   [KK][LL];
__device__ float gmuSq[KK];
__device__ float giD [KK];
__device__ float gck[KK];
__device__ float gs2[KK];
__device__ float grsum[KK];
__device__ float grx2[KK];

// ---------------- helpers ----------------
__device__ __forceinline__ uint32_t s2u(const void* p) {
    uint32_t a;
    asm("{ .reg .u64 t; cvta.to.shared.u64 t, %1; cvt.u32.u64 %0, t; }" : "=r"(a) : "l"(p));
    return a;
}
__device__ __forceinline__ void ldm4(uint32_t* r, uint32_t addr) {
    asm volatile("ldmatrix.sync.aligned.m8n8.x4.shared.b16 {%0,%1,%2,%3}, [%4];"
                 : "=r"(r[0]), "=r"(r[1]), "=r"(r[2]), "=r"(r[3]) : "r"(addr));
}
__device__ __forceinline__ void mma16816(float* c, const uint32_t* a, uint32_t b0, uint32_t b1) {
    asm volatile(
        "mma.sync.aligned.m16n8k16.row.col.f32.bf16.bf16.f32 "
        "{%0,%1,%2,%3}, {%4,%5,%6,%7}, {%8,%9}, {%0,%1,%2,%3};"
        : "+f"(c[0]), "+f"(c[1]), "+f"(c[2]), "+f"(c[3])
        : "r"(a[0]), "r"(a[1]), "r"(a[2]), "r"(a[3]), "r"(b0), "r"(b1));
}
__device__ __forceinline__ void cpasync16(uint32_t smem, const void* g) {
    asm volatile("cp.async.cg.shared.global [%0], [%1], 16;" :: "r"(smem), "l"(g) : "memory");
}
#define CP_COMMIT() asm volatile("cp.async.commit_group;" ::: "memory")
#define CP_WAIT2()  asm volatile("cp.async.wait_group 2;" ::: "memory")

__device__ __forceinline__ float block_reduce_sum(float v, float* sbuf) {
    int t = threadIdx.x;
    sbuf[t] = v; __syncthreads();
    for (int s = 128; s > 0; s >>= 1) {
        if (t < s) sbuf[t] += sbuf[t + s];
        __syncthreads();
    }
    float r = sbuf[0];
    __syncthreads();
    return r;
}
__device__ void block_invert16(float aug[16][32], float* slogdet, float* sfac, int* spiv) {
    int t = threadIdx.x;
    int r = t >> 4, c = t & 15;
    for (int p = 0; p < 16; ++p) {
        __syncthreads();
        if (t < 32) {
            float v = (t < 16 && t >= p) ? fabsf(aug[t][p]) : -1.f;
            int idx = t;
            #pragma unroll
            for (int off = 8; off > 0; off >>= 1) {
                float ov = __shfl_xor_sync(0xffffffffu, v, off);
                int oi = __shfl_xor_sync(0xffffffffu, idx, off);
                if (ov > v) { v = ov; idx = oi; }
            }
            if (t == 0) {
                *spiv = idx;
                if (slogdet) *slogdet += logf(fmaxf(v, 1e-30f));
            }
        }
        __syncthreads();
        int pr = *spiv;
        if (pr != p && t < 32) { float tmp = aug[p][t]; aug[p][t] = aug[pr][t]; aug[pr][t] = tmp; }
        __syncthreads();
        if (t < 32) {
            float val = aug[p][t];
            float pv  = aug[p][p];
            __syncwarp();
            aug[p][t] = val / pv;
        }
        __syncthreads();
        if (c == 0) sfac[r] = aug[r][p];
        __syncthreads();
        if (r != p) {
            float f = sfac[r];
            aug[r][c]      -= f * aug[p][c];
            aug[r][c + 16] -= f * aug[p][c + 16];
        }
    }
    __syncthreads();
}

// ---------------- kernel 0: zero scratch (side stream) ----------------
__global__ void zero_kernel() {
    int i0 = blockIdx.x * 256 + threadIdx.x;
    int str = gridDim.x * 256;
    for (int i = i0; i < DD * KK; i += str) (&gMuNum[0][0])[i] = 0.f;
    if (i0 < KK) { grsum[i0] = 0.f; grx2[i0] = 0.f; }
    if (i0 < KK * LL) (&gG[0][0])[i0] = 0.f;
}

// ---------------- straight split + x2 (critical path) ----------------
__global__ void __launch_bounds__(256) xprep_straight(const float* __restrict__ x) {
    int warp = threadIdx.x >> 5, lane = threadIdx.x & 31;
    int n = blockIdx.x * 8 + warp;
    const float4* xr = (const float4*)(x + (size_t)n * DD);
    float s = 0.f;
    #pragma unroll
    for (int c = lane; c < 256; c += 32) {
        float4 v = xr[c];
        s += v.x * v.x + v.y * v.y + v.z * v.z + v.w * v.w;
        __nv_bfloat16 h0 = __float2bfloat16(v.x), h1 = __float2bfloat16(v.y);
        __nv_bfloat16 h2 = __float2bfloat16(v.z), h3 = __float2bfloat16(v.w);
        ushort4 ph, pl;
        ph.x = __bfloat16_as_ushort(h0); ph.y = __bfloat16_as_ushort(h1);
        ph.z = __bfloat16_as_ushort(h2); ph.w = __bfloat16_as_ushort(h3);
        pl.x = __bfloat16_as_ushort(__float2bfloat16(v.x - __bfloat162float(h0)));
        pl.y = __bfloat16_as_ushort(__float2bfloat16(v.y - __bfloat162float(h1)));
        pl.z = __bfloat16_as_ushort(__float2bfloat16(v.z - __bfloat162float(h2)));
        pl.w = __bfloat16_as_ushort(__float2bfloat16(v.w - __bfloat162float(h3)));
        *(ushort4*)(&gXhi[n][c * 4]) = ph;
        *(ushort4*)(&gXlo[n][c * 4]) = pl;
    }
    #pragma unroll
    for (int off = 16; off > 0; off >>= 1) s += __shfl_xor_sync(0xffffffffu, s, off);
    if (lane == 0) gX2[n] = s;
}

// ---------------- transposed split (side stream 1) ----------------
__global__ void __launch_bounds__(256) xprep_T(const float* __restrict__ x) {
    __shared__ float tile[32][33];
    int t = threadIdx.x;
    int tx8 = t & 7, ty = t >> 3;
    int c0 = blockIdx.x * 32, r0 = blockIdx.y * 32;
    float4 v = *(const float4*)(x + (size_t)(r0 + ty) * DD + c0 + tx8 * 4);
    tile[ty][tx8 * 4 + 0] = v.x;
    tile[ty][tx8 * 4 + 1] = v.y;
    tile[ty][tx8 * 4 + 2] = v.z;
    tile[ty][tx8 * 4 + 3] = v.w;
    __syncthreads();
    int cc = t >> 3, rq = (t & 7) * 4;
    float w0 = tile[rq + 0][cc], w1 = tile[rq + 1][cc];
    float w2 = tile[rq + 2][cc], w3 = tile[rq + 3][cc];
    __nv_bfloat16 g0 = __float2bfloat16(w0), g1 = __float2bfloat16(w1);
    __nv_bfloat16 g2 = __float2bfloat16(w2), g3 = __float2bfloat16(w3);
    ushort4 qh, ql;
    qh.x = __bfloat16_as_ushort(g0); qh.y = __bfloat16_as_ushort(g1);
    qh.z = __bfloat16_as_ushort(g2); qh.w = __bfloat16_as_ushort(g3);
    ql.x = __bfloat16_as_ushort(__float2bfloat16(w0 - __bfloat162float(g0)));
    ql.y = __bfloat16_as_ushort(__float2bfloat16(w1 - __bfloat162float(g1)));
    ql.z = __bfloat16_as_ushort(__float2bfloat16(w2 - __bfloat162float(g2)));
    ql.w = __bfloat16_as_ushort(__float2bfloat16(w3 - __bfloat162float(g3)));
    *(ushort4*)(&gXThi[c0 + cc][r0 + rq]) = qh;
    *(ushort4*)(&gXTlo[c0 + cc][r0 + rq]) = ql;
}

// ---------------- per-k setup (side stream 2), 64-row-chunked ----------------
__global__ void setup_kernel(const float* __restrict__ MU, const float* __restrict__ A,
                             const float* __restrict__ log_D, const float* __restrict__ PI_logits) {
    int k = blockIdx.x, t = threadIdx.x;
    __shared__ float sred[256];
    __shared__ float sPIk;
    if (t == 0) {
        float mx = -1e30f;
        for (int j = 0; j < KK; ++j) mx = fmaxf(mx, PI_logits[j]);
        float s = 0.f;
        for (int j = 0; j < KK; ++j) s += expf(PI_logits[j] - mx);
        sPIk = expf(PI_logits[k] - mx) / s;
    }
    float ld0 = log_D[(size_t)k * DD];
    float iD = expf(-ld0);
    float s2 = expf(ld0);
    float muSqAcc = 0.f;
    for (int d = t; d < DD; d += 256) {
        float mu = MU[(size_t)k * DD + d];
        __nv_bfloat16 h = __float2bfloat16(mu);
        gWThi[k][d] = h;
        gWTlo[k][d] = __float2bfloat16(mu - __bfloat162float(h));
        muSqAcc += mu * mu;
    }
    __shared__ float sA[64][17];
    int li = t >> 4, mi = t & 15;
    float ATAacc = 0.f, bmuAcc = 0.f;
    const int lw = t >> 4;
    const int dq = (t & 15) * 4;
    for (int c0 = 0; c0 < DD; c0 += 64) {
        __syncthreads();
        {
            int row = t >> 2, q = (t & 3) * 4;
            float4 a4 = *(const float4*)(A + ((size_t)k * DD + c0 + row) * LL + q);
            sA[row][q + 0] = a4.x;
            sA[row][q + 1] = a4.y;
            sA[row][q + 2] = a4.z;
            sA[row][q + 3] = a4.w;
        }
        __syncthreads();
        {
            float4 m4 = *(const float4*)(MU + (size_t)k * DD + c0 + dq);
            float a0 = sA[dq + 0][lw], a1 = sA[dq + 1][lw];
            float a2 = sA[dq + 2][lw], a3 = sA[dq + 3][lw];
            bmuAcc += m4.x * a0 + m4.y * a1 + m4.z * a2 + m4.w * a3;
            __nv_bfloat16 h0 = __float2bfloat16(a0), h1 = __float2bfloat16(a1);
            __nv_bfloat16 h2 = __float2bfloat16(a2), h3 = __float2bfloat16(a3);
            ushort4 ph, pl;
            ph.x = __bfloat16_as_ushort(h0); ph.y = __bfloat16_as_ushort(h1);
            ph.z = __bfloat16_as_ushort(h2); ph.w = __bfloat16_as_ushort(h3);
            pl.x = __bfloat16_as_ushort(__float2bfloat16(a0 - __bfloat162float(h0)));
            pl.y = __bfloat16_as_ushort(__float2bfloat16(a1 - __bfloat162float(h1)));
            pl.z = __bfloat16_as_ushort(__float2bfloat16(a2 - __bfloat162float(h2)));
            pl.w = __bfloat16_as_ushort(__float2bfloat16(a3 - __bfloat162float(h3)));
            *(ushort4*)(&gWThi[32 + k * 16 + lw][c0 + dq]) = ph;
            *(ushort4*)(&gWTlo[32 + k * 16 + lw][c0 + dq]) = pl;
        }
        #pragma unroll
        for (int dd = 0; dd < 64; ++dd) ATAacc += sA[dd][li] * sA[dd][mi];
    }
    float muSqK = block_reduce_sum(muSqAcc, sred);
    __shared__ float sbm[16][17];
    sbm[lw][t & 15] = bmuAcc;
    __syncthreads();
    if (t < 16) {
        float s = 0.f;
        for (int g = 0; g < 16; ++g) s += sbm[t][g];
        gbmu[k][t] = s;
    }
    __shared__ float aug[16][32];
    __shared__ float sfac[16];
    __shared__ int spiv;
    __shared__ float slogdet;
    if (t == 0) slogdet = 0.f;
    __syncthreads();
    aug[li][mi]      = iD * ATAacc + (li == mi ? 1.f : 0.f);
    aug[li][16 + mi] = (li == mi ? 1.f : 0.f);
    block_invert16(aug, &slogdet, sfac, &spiv);
    giL[k][li][mi] = aug[li][16 + mi];
    float logdetL = slogdet;
    __syncthreads();
    aug[li][mi]      = ATAacc + (li == mi ? s2 : 0.f);
    aug[li][16 + mi] = (li == mi ? 1.f : 0.f);
    block_invert16(aug, nullptr, sfac, &spiv);
    gInvM[k][li][mi] = aug[li][16 + mi];
    if (t == 0) {
        gmuSq[k] = muSqK;
        giD[k] = iD;
        gs2[k] = s2;
        gck[k] = sPIk - 0.5f * ((float)DD * LOG2PI_F + logdetL + (float)DD * ld0);
    }
}

// ---------------- fused mma GEMM: fat 128x128 tiles (y<4) + skinny 128x32 (y==4) ----------------
#define SR16 24
#define STG_AHI 0
#define STG_ALO 6144
#define STG_BHI 12288
#define STG_BLO 18432
#define STGSZ   24576
#define NSTAGE  4

__global__ void __launch_bounds__(256, 2) mma_gemm_fused(
    const __nv_bfloat16* __restrict__ Ahi, const __nv_bfloat16* __restrict__ Alo, int lda,
    const __nv_bfloat16* __restrict__ Bhi, const __nv_bfloat16* __restrict__ Blo, int ldb,
    float* __restrict__ C, int ldc, int zstride, int nOffFat,
    float* __restrict__ Cs, int ldcs, int zstrideS, int bOffS, int atomicS,
    int kLen)
{
    extern __shared__ __align__(128) char ds[];
    const uint32_t sbase = s2u(ds);
    const int t = threadIdx.x, lane = t & 31, w = t >> 5;
    const int m0 = blockIdx.x * 128;
    const int kBeg = blockIdx.z * kLen;
    const int nCh = kLen >> 4;

    if (blockIdx.y < 4) {
        const int wm = w & 1, wn = w >> 1;
        const int n0 = nOffFat + blockIdx.y * 128;
        float* Cf = C + (size_t)blockIdx.z * zstride;

        const int row = t >> 1, half = (t & 1) * 8;
        const size_t gA = (size_t)(m0 + row) * lda + kBeg + half;
        const size_t gB = (size_t)(n0 + row) * ldb + kBeg + half;
        const uint32_t soff = (uint32_t)(row * SR16 + half) * 2;
        const int aoff0 = ((wm * 64 + (lane & 15)) * SR16 + ((lane >> 4) << 3)) * 2;
        const int boff0 = ((wn * 32 + (lane & 15)) * SR16 + ((lane >> 4) << 3)) * 2;

        float acc[4][4][4] = {};

        #pragma unroll
        for (int st = 0; st < NSTAGE - 1; ++st) {
            uint32_t sb = sbase + st * STGSZ;
            int kk = st * 16;
            cpasync16(sb + STG_AHI + soff, Ahi + gA + kk);
            cpasync16(sb + STG_ALO + soff, Alo + gA + kk);
            cpasync16(sb + STG_BHI + soff, Bhi + gB + kk);
            cpasync16(sb + STG_BLO + soff, Blo + gB + kk);
            CP_COMMIT();
        }
        for (int ch = 0; ch < nCh; ++ch) {
            CP_WAIT2();
            __syncthreads();
            const uint32_t sb = sbase + (ch & 3) * STGSZ;
            uint32_t ah[4][4], al[4][4], bh[2][4], bl[2][4];
            #pragma unroll
            for (int p = 0; p < 2; ++p) {
                ldm4(bh[p], sb + STG_BHI + boff0 + p * 16 * SR16 * 2);
                ldm4(bl[p], sb + STG_BLO + boff0 + p * 16 * SR16 * 2);
            }
            #pragma unroll
            for (int mf = 0; mf < 4; ++mf) {
                ldm4(ah[mf], sb + STG_AHI + aoff0 + mf * 16 * SR16 * 2);
                ldm4(al[mf], sb + STG_ALO + aoff0 + mf * 16 * SR16 * 2);
            }
            #pragma unroll
            for (int mf = 0; mf < 4; ++mf)
                #pragma unroll
                for (int nf = 0; nf < 4; ++nf) {
                    int p = nf >> 1, o = nf & 1;
                    mma16816(acc[mf][nf], ah[mf], bh[p][o], bh[p][2 + o]);
                }
            #pragma unroll
            for (int mf = 0; mf < 4; ++mf)
                #pragma unroll
                for (int nf = 0; nf < 4; ++nf) {
                    int p = nf >> 1, o = nf & 1;
                    mma16816(acc[mf][nf], ah[mf], bl[p][o], bl[p][2 + o]);
                }
            #pragma unroll
            for (int mf = 0; mf < 4; ++mf)
                #pragma unroll
                for (int nf = 0; nf < 4; ++nf) {
                    int p = nf >> 1, o = nf & 1;
                    mma16816(acc[mf][nf], al[mf], bh[p][o], bh[p][2 + o]);
                }
            int st = ch + NSTAGE - 1;
            if (st < nCh) {
                uint32_t sn = sbase + (st & 3) * STGSZ;
                int kk = st * 16;
                cpasync16(sn + STG_AHI + soff, Ahi + gA + kk);
                cpasync16(sn + STG_ALO + soff, Alo + gA + kk);
                cpasync16(sn + STG_BHI + soff, Bhi + gB + kk);
                cpasync16(sn + STG_BLO + soff, Blo + gB + kk);
            }
            CP_COMMIT();
        }
        const int gid = lane >> 2, tid = lane & 3;
        #pragma unroll
        for (int mf = 0; mf < 4; ++mf) {
            #pragma unroll
            for (int nf = 0; nf < 4; ++nf) {
                int rr = m0 + wm * 64 + mf * 16 + gid;
                int col = n0 + wn * 32 + nf * 8 + tid * 2;
                float* c0 = Cf + (size_t)rr * ldc + col;
                float* c1 = Cf + (size_t)(rr + 8) * ldc + col;
                *(float2*)c0 = make_float2(acc[mf][nf][0], acc[mf][nf][1]);
                *(float2*)c1 = make_float2(acc[mf][nf][2], acc[mf][nf][3]);
            }
        }
    } else {
        const int wm = w >> 1, wn = w & 1;
        float* Csf = Cs + (size_t)blockIdx.z * zstrideS;
        const int row = t >> 1, half = (t & 1) * 8;
        const size_t gA = (size_t)(m0 + row) * lda + kBeg + half;
        const uint32_t soffA = (uint32_t)(row * SR16 + half) * 2;
        const int rowB = (t & 63) >> 1;
        const size_t gB = (size_t)(bOffS + rowB) * ldb + kBeg + half;
        const uint32_t soffB = (uint32_t)(rowB * SR16 + half) * 2;
        const bool doB = (t < 64);
        const int aoff0 = ((wm * 32 + (lane & 15)) * SR16 + ((lane >> 4) << 3)) * 2;
        const int boff0 = ((wn * 16 + (lane & 15)) * SR16 + ((lane >> 4) << 3)) * 2;

        float acc[2][2][4] = {};

        #pragma unroll
        for (int st = 0; st < NSTAGE - 1; ++st) {
            uint32_t sb = sbase + st * STGSZ;
            int kk = st * 16;
            cpasync16(sb + STG_AHI + soffA, Ahi + gA + kk);
            cpasync16(sb + STG_ALO + soffA, Alo + gA + kk);
            if (doB) {
                cpasync16(sb + STG_BHI + soffB, Bhi + gB + kk);
                cpasync16(sb + STG_BLO + soffB, Blo + gB + kk);
            }
            CP_COMMIT();
        }
        for (int ch = 0; ch < nCh; ++ch) {
            CP_WAIT2();
            __syncthreads();
            const uint32_t sb = sbase + (ch & 3) * STGSZ;
            uint32_t ah[2][4], al[2][4], bh[4], bl[4];
            ldm4(bh, sb + STG_BHI + boff0);
            ldm4(bl, sb + STG_BLO + boff0);
            #pragma unroll
            for (int mf = 0; mf < 2; ++mf) {
                ldm4(ah[mf], sb + STG_AHI + aoff0 + mf * 16 * SR16 * 2);
                ldm4(al[mf], sb + STG_ALO + aoff0 + mf * 16 * SR16 * 2);
            }
            #pragma unroll
            for (int mf = 0; mf < 2; ++mf)
                #pragma unroll
                for (int nf = 0; nf < 2; ++nf)
                    mma16816(acc[mf][nf], ah[mf], bh[nf], bh[2 + nf]);
            #pragma unroll
            for (int mf = 0; mf < 2; ++mf)
                #pragma unroll
                for (int nf = 0; nf < 2; ++nf)
                    mma16816(acc[mf][nf], ah[mf], bl[nf], bl[2 + nf]);
            #pragma unroll
            for (int mf = 0; mf < 2; ++mf)
                #pragma unroll
                for (int nf = 0; nf < 2; ++nf)
                    mma16816(acc[mf][nf], al[mf], bh[nf], bh[2 + nf]);
            int st = ch + NSTAGE - 1;
            if (st < nCh) {
                uint32_t sn = sbase + (st & 3) * STGSZ;
                int kk = st * 16;
                cpasync16(sn + STG_AHI + soffA, Ahi + gA + kk);
                cpasync16(sn + STG_ALO + soffA, Alo + gA + kk);
                if (doB) {
                    cpasync16(sn + STG_BHI + soffB, Bhi + gB + kk);
                    cpasync16(sn + STG_BLO + soffB, Blo + gB + kk);
                }
            }
            CP_COMMIT();
        }
        const int gid = lane >> 2, tid = lane & 3;
        #pragma unroll
        for (int mf = 0; mf < 2; ++mf) {
            #pragma unroll
            for (int nf = 0; nf < 2; ++nf) {
                int rr = m0 + wm * 32 + mf * 16 + gid;
                int col = wn * 16 + nf * 8 + tid * 2;
                float* c0 = Csf + (size_t)rr * ldcs + col;
                float* c1 = Csf + (size_t)(rr + 8) * ldcs + col;
                if (atomicS) {
                    atomicAdd(c0,     acc[mf][nf][0]);
                    atomicAdd(c0 + 1, acc[mf][nf][1]);
                    atomicAdd(c1,     acc[mf][nf][2]);
                    atomicAdd(c1 + 1, acc[mf][nf][3]);
                } else {
                    *(float2*)c0 = make_float2(acc[mf][nf][0], acc[mf][nf][1]);
                    *(float2*)c1 = make_float2(acc[mf][nf][2], acc[mf][nf][3]);
                }
            }
        }
    }
}

// ---------------- E-step epilogue (sums the ZC gC slabs) ----------------
__global__ void __launch_bounds__(256) estep_epilogue() {
    __shared__ float siLs[KK * 272];
    __shared__ float sbmu_[KK][LL];
    __shared__ float smuSq_[KK];
    __shared__ float siD_[KK];
    __shared__ float sck_[KK];
    __shared__ float sll[8][32];
    int t = threadIdx.x;
    for (int idx = t; idx < KK * 256; idx += 256) {
        int kk = idx >> 8, rem = idx & 255;
        siLs[kk * 272 + (rem >> 4) * 17 + (rem & 15)] = (&giL[0][0][0])[idx];
    }
    for (int idx = t; idx < KK * LL; idx += 256) (&sbmu_[0][0])[idx] = (&gbmu[0][0])[idx];
    if (t < KK) { smuSq_[t] = gmuSq[t]; sck_[t] = gck[t]; siD_[t] = giD[t]; }
    __syncthreads();

    int warp = t >> 5, lane = t & 31;
    int n = blockIdx.x * 8 + warp;
    const float* C0 = &gCs[0][n][0];
    const float* C1 = &gCs[1][n][0];
    float x2 = gX2[n];
    #pragma unroll 1
    for (int it = 0; it < 16; ++it) {
        int k = it * 2 + (lane >> 4);
        int gl = lane & 15;
        int jj = 32 + k * 16 + gl;
        float yv = C0[jj] + C1[jj] - sbmu_[k][gl];
        float z = 0.f;
        const float* ilr = &siLs[k * 272 + gl * 17];
        #pragma unroll
        for (int m = 0; m < 16; ++m) {
            float ym = __shfl_sync(0xffffffffu, yv, (lane & 16) | m);
            z += ilr[m] * ym;
        }
        float t2 = z * yv;
        #pragma unroll
        for (int off = 8; off > 0; off >>= 1) t2 += __shfl_xor_sync(0xffffffffu, t2, off);
        if (gl == 0) {
            float iD = siD_[k];
            float cross = C0[k] + C1[k];
            float term1 = iD * (x2 - 2.f * cross + smuSq_[k]);
            sll[warp][k] = sck_[k] - 0.5f * term1 + 0.5f * iD * iD * t2;
        }
    }
    __syncwarp();
    float llk = sll[warp][lane];
    float mx = llk;
    #pragma unroll
    for (int off = 16; off > 0; off >>= 1) mx = fmaxf(mx, __shfl_xor_sync(0xffffffffu, mx, off));
    float e = expf(llk - mx);
    float s = e;
    #pragma unroll
    for (int off = 16; off > 0; off >>= 1) s += __shfl_xor_sync(0xffffffffu, s, off);
    float r = e / s;
    float* Mrow = &gM2[n][0];
    Mrow[512 + lane] = r;
    Mrow[544 + lane] = r * x2;
    #pragma unroll
    for (int it = 0; it < 16; ++it) {
        int j = it * 32 + lane;
        float rk = __shfl_sync(0xffffffffu, r, j >> 4);
        Mrow[j] = rk * (C0[32 + j] + C1[32 + j]);
    }
}

// ---------------- transpose-split M2 + fused column sums ----------------
__global__ void __launch_bounds__(256) tsplit_m2_kernel() {
    __shared__ float tile[32][33];
    int t = threadIdx.x;
    int tx = t & 31, ty = t >> 5;
    int c0 = blockIdx.x * 32;
    int r0 = blockIdx.y * 32;
    #pragma unroll
    for (int j = 0; j < 32; j += 8)
        tile[ty + j][tx] = gM2[r0 + ty + j][c0 + tx];
    __syncthreads();
    #pragma unroll
    for (int j = 0; j < 32; j += 8) {
        int wcol = c0 + ty + j;
        int h = r0 + tx;
        float v = tile[tx][ty + j];
        __nv_bfloat16 hi = __float2bfloat16(v);
        gM2Thi[wcol][h] = hi;
        gM2Tlo[wcol][h] = __float2bfloat16(v - __bfloat162float(hi));
    }
    if (t < 32) {
        int col = c0 + t;
        float s = 0.f;
        #pragma unroll
        for (int rr = 0; rr < 32; ++rr) s += tile[rr][t];
        if (col < 512)      atomicAdd(&gG[0][0] + col, s);
        else if (col < 544) atomicAdd(&grsum[col - 512], s);
        else                atomicAdd(&grx2[col - 544], s);
    }
}

// ---------------- finalize: sum ZD slabs, mu + SiAi ----------------
__global__ void __launch_bounds__(256) finalize_kernel(float* __restrict__ outMu) {
    __shared__ float sums[8][512];
    int t = threadIdx.x, warp = t >> 5, lane = t & 31;
    int d = blockIdx.x * 8 + warp;
    const float* base = &gSiAiP[d][0][0];
    for (int c = lane; c < 512; c += 32) {
        float s = 0.f;
        #pragma unroll
        for (int j = 0; j < ZD; ++j) s += base[j * 512 + c];
        sums[warp][c] = s;
    }
    {
        int k = lane;
        float mu = gMuNum[d][k] / grsum[k];
        gmu[k][d] = mu;
        outMu[k * DD + d] = mu;
    }
    __syncwarp();
    for (int c = lane; c < 512; c += 32) {
        int k = c >> 4, l = c & 15;
        float rs = grsum[k];
        float mu = gMuNum[d][k] / rs;
        gSiAi2[k][d][l] = (sums[warp][c] - mu * gG[k][l]) / rs;
    }
}

// ---------------- per-k M-step (64-row-chunked) ----------------
__global__ void __launch_bounds__(256) mstep_kernel(const float* __restrict__ A,
                                                    float* __restrict__ outA,
                                                    float* __restrict__ outLogD,
                                                    float* __restrict__ outPI) {
    int k = blockIdx.x, t = threadIdx.x;
    int li = t >> 4, mi = t & 15;
    __shared__ float sS[64][17];
    __shared__ float sAs[64][17];
    float acc = 0.f;
    const int lrow = t >> 2, lq = (t & 3) * 4;   // chunk-load geometry
    for (int d0 = 0; d0 < DD; d0 += 64) {
        __syncthreads();
        {
            float4 a4 = *(const float4*)(A + ((size_t)k * DD + d0 + lrow) * LL + lq);
            sAs[lrow][lq + 0] = a4.x; sAs[lrow][lq + 1] = a4.y;
            sAs[lrow][lq + 2] = a4.z; sAs[lrow][lq + 3] = a4.w;
            float4 s4 = *(const float4*)(&gSiAi2[k][d0 + lrow][lq]);
            sS[lrow][lq + 0] = s4.x; sS[lrow][lq + 1] = s4.y;
            sS[lrow][lq + 2] = s4.z; sS[lrow][lq + 3] = s4.w;
        }
        __syncthreads();
        #pragma unroll
        for (int dd = 0; dd < 64; ++dd) acc += sAs[dd][li] * sS[dd][mi];
    }
    __shared__ float sATS[16][16];
    __shared__ float siM[16][16];
    __syncthreads();
    sATS[li][mi] = acc;
    siM[li][mi] = gInvM[k][li][mi];
    __syncthreads();
    float Tv = 0.f;
    #pragma unroll
    for (int j = 0; j < 16; ++j) Tv += siM[li][j] * sATS[j][mi];
    __shared__ float aug[16][32];
    __shared__ float sfac[16];
    __shared__ int spiv;
    aug[li][mi]      = Tv + (li == mi ? gs2[k] : 0.f);
    aug[li][16 + mi] = (li == mi ? 1.f : 0.f);
    block_invert16(aug, nullptr, sfac, &spiv);
    __shared__ float sW2[16][16];
    sW2[li][mi] = aug[li][16 + mi];
    __syncthreads();
    float t1acc = 0.f;
    for (int d0 = 0; d0 < DD; d0 += 64) {
        __syncthreads();
        {
            float4 s4 = *(const float4*)(&gSiAi2[k][d0 + lrow][lq]);
            sS[lrow][lq + 0] = s4.x; sS[lrow][lq + 1] = s4.y;
            sS[lrow][lq + 2] = s4.z; sS[lrow][lq + 3] = s4.w;
        }
        __syncthreads();
        #pragma unroll
        for (int rr = 0; rr < 4; ++rr) {
            int row = rr * 16 + li;
            float an = 0.f, sim = 0.f;
            #pragma unroll
            for (int m = 0; m < 16; ++m) {
                float sv = sS[row][m];
                an  += sv * sW2[m][mi];
                sim += sv * siM[m][mi];
            }
            outA[((size_t)k * DD + d0 + row) * LL + mi] = an;
            t1acc += an * sim;
        }
    }
    float msq = 0.f;
    for (int d = t; d < DD; d += 256) { float m = gmu[k][d]; msq += m * m; }
    __shared__ float sred[256];
    float t1   = block_reduce_sum(t1acc, sred);
    float msqs = block_reduce_sum(msq, sred);
    __shared__ float sld;
    if (t == 0) {
        float rs = grsum[k];
        float traceS = (grx2[k] - rs * msqs) / rs;
        float sig2 = (traceS - t1) / (float)DD;
        sld = logf(sig2);
        float tot = 0.f;
        for (int j = 0; j < KK; ++j) tot += grsum[j];
        outPI[k] = logf(grsum[k] / tot);
    }
    __syncthreads();
    float ldv = sld;
    for (int d = t; d < DD; d += 256) outLogD[k * DD + d] = ldv;
}

// ---------------- launch ----------------
extern "C" void kernel_launch(void* const* d_in, const int* in_sizes, int n_in,
                              void* d_out, int out_size) {
    const float* x   = (const float*)d_in[0];
    const float* MU  = (const float*)d_in[1];
    const float* A   = (const float*)d_in[2];
    const float* lD  = (const float*)d_in[3];
    const float* PIl = (const float*)d_in[4];
    float* out = (float*)d_out;
    float* outMu   = out;
    float* outA    = out + KK * DD;
    float* outLogD = out + KK * DD + KK * DD * LL;
    float* outPI   = out + KK * DD + KK * DD * LL + KK * DD;

    const int DSMEM = NSTAGE * STGSZ;   // 98304
    static int inited = 0;
    static cudaStream_t sSide1, sSide2;
    static cudaEvent_t evFork, evT, evS;
    if (!inited) {
        cudaFuncSetAttribute(mma_gemm_fused, cudaFuncAttributeMaxDynamicSharedMemorySize, DSMEM);
        cudaStreamCreateWithFlags(&sSide1, cudaStreamNonBlocking);
        cudaStreamCreateWithFlags(&sSide2, cudaStreamNonBlocking);
        cudaEventCreateWithFlags(&evFork, cudaEventDisableTiming);
        cudaEventCreateWithFlags(&evT, cudaEventDisableTiming);
        cudaEventCreateWithFlags(&evS, cudaEventDisableTiming);
        inited = 1;
    }

    __nv_bfloat16 *pXhi, *pXlo, *pXThi, *pXTlo, *pWThi, *pWTlo, *pM2Thi, *pM2Tlo;
    float *pCs, *pSiAiP, *pMuNum;
    cudaGetSymbolAddress((void**)&pXhi,   gXhi);
    cudaGetSymbolAddress((void**)&pXlo,   gXlo);
    cudaGetSymbolAddress((void**)&pXThi,  gXThi);
    cudaGetSymbolAddress((void**)&pXTlo,  gXTlo);
    cudaGetSymbolAddress((void**)&pWThi,  gWThi);
    cudaGetSymbolAddress((void**)&pWTlo,  gWTlo);
    cudaGetSymbolAddress((void**)&pM2Thi, gM2Thi);
    cudaGetSymbolAddress((void**)&pM2Tlo, gM2Tlo);
    cudaGetSymbolAddress((void**)&pCs,    gCs);
    cudaGetSymbolAddress((void**)&pSiAiP, gSiAiP);
    cudaGetSymbolAddress((void**)&pMuNum, gMuNum);

    // fork
    cudaEventRecord(evFork, 0);
    cudaStreamWaitEvent(sSide1, evFork, 0);
    cudaStreamWaitEvent(sSide2, evFork, 0);
    xprep_T<<<dim3(DD / 32, NN / 32), 256, 0, sSide1>>>(x);
    cudaEventRecord(evT, sSide1);
    zero_kernel<<<128, 256, 0, sSide2>>>();
    setup_kernel<<<KK, 256, 0, sSide2>>>(MU, A, lD, PIl);
    cudaEventRecord(evS, sSide2);

    // main stream
    xprep_straight<<<NN / 8, 256>>>(x);
    cudaStreamWaitEvent(0, evS, 0);
    mma_gemm_fused<<<dim3(NN / 128, 5, ZC), 256, DSMEM>>>(
        pXhi, pXlo, DD, pWThi, pWTlo, DD,
        pCs, WPAD, NN * WPAD, 32,
        pCs, WPAD, NN * WPAD, 0, 0,
        DD / ZC);
    estep_epilogue<<<NN / 8, 256>>>();
    tsplit_m2_kernel<<<dim3(M2W / 32, NN / 32), 256>>>();
    cudaStreamWaitEvent(0, evT, 0);
    mma_gemm_fused<<<dim3(DD / 128, 5, ZD), 256, DSMEM>>>(
        pXThi, pXTlo, NN, pM2Thi, pM2Tlo, NN,
        pSiAiP, ZD * 512, 512, 0,
        pMuNum, KK, 0, 512, 1,
        NN / ZD);
    finalize_kernel<<<DD / 8, 256>>>(outMu);
    mstep_kernel<<<KK, 256>>>(A, outA, outLogD, outPI);
}